// round 1
// baseline (speedup 1.0000x reference)
#include <cuda_runtime.h>
#include <cstdint>

// ---------------------------------------------------------------------------
// Problem constants (all fixed by the reference)
// ---------------------------------------------------------------------------
constexpr int R_ = 64;          // num_rows
constexpr int C_ = 512;         // num_cols (sequence for attention)
constexpr int H_ = 12;          // heads
constexpr int D_ = 64;          // head_dim
constexpr int E_ = 768;         // embed
constexpr int M_TOK = R_ * C_;  // 32768 tokens
constexpr int RD   = R_ * D_;   // 4096  (tied contraction length)
constexpr int HRD  = H_ * RD;   // 49152 (row stride of [C,H,R,D] layout)

constexpr long OUT_OFF_P = (long)M_TOK * E_;            // 25,165,824
constexpr long OUT_OFF_L = OUT_OFF_P + (long)H_ * C_ * C_; // 28,311,552

constexpr float SCALING = 0.015625f; // D^-0.5 / sqrt(R) = (1/8)/8

// ---------------------------------------------------------------------------
// Scratch (static __device__ arrays — no allocation allowed)
// ---------------------------------------------------------------------------
__device__ float g_Q[(long)C_ * H_ * R_ * D_];   // 96 MB, layout [i][h][r][d]
__device__ float g_K[(long)C_ * H_ * R_ * D_];   // 96 MB
__device__ float g_V[(long)C_ * H_ * R_ * D_];   // 96 MB
__device__ float g_S[(long)H_ * C_ * C_];        // 12 MB  logits
__device__ float g_P[(long)H_ * C_ * C_];        // 12 MB  probs
__device__ float g_ctx[(long)M_TOK * E_];        // 96 MB, layout [m][e]

// ---------------------------------------------------------------------------
// Classic 128x128x8 fp32 SGEMM, NT variant (C = A * B^T), 256 threads,
// 8x8 register tile per thread. All shapes divide exactly; no bounds checks.
// ---------------------------------------------------------------------------
constexpr int BM = 128, BN = 128, BK = 8;

enum EpiMode { EPI_QKV = 0, EPI_LOGITS = 1, EPI_OPROJ = 2 };

template <int EPI>
__global__ void __launch_bounds__(256)
gemm_nt_kernel(const float* __restrict__ A, const float* __restrict__ B,
               const float* __restrict__ bias, float* __restrict__ Cout,
               int lda, int ldb, float scale)
{
    __shared__ float As[BK][BM];
    __shared__ float Bs[BK][BN];

    const int tid = threadIdx.x;
    const int m0 = blockIdx.y * BM;
    const int n0 = blockIdx.x * BN;
    const int z  = blockIdx.z;

    if (EPI == EPI_LOGITS) { A += (size_t)z * RD; B += (size_t)z * RD; }
    const int K = (EPI == EPI_LOGITS) ? RD : E_;

    const int arow = tid >> 1;          // 0..127
    const int acol = (tid & 1) * 4;     // 0 or 4
    const float* Ag = A + (size_t)(m0 + arow) * lda + acol;
    const float* Bg = B + (size_t)(n0 + arow) * ldb + acol;

    const int ty = tid >> 4;            // 0..15 -> m rows ty*8
    const int tx = tid & 15;            // 0..15 -> n cols tx*8

    float acc[8][8];
#pragma unroll
    for (int i = 0; i < 8; i++)
#pragma unroll
        for (int j = 0; j < 8; j++) acc[i][j] = 0.f;

    for (int k0 = 0; k0 < K; k0 += BK) {
        float4 av = *(const float4*)(Ag + k0);
        float4 bv = *(const float4*)(Bg + k0);
        As[acol + 0][arow] = av.x; As[acol + 1][arow] = av.y;
        As[acol + 2][arow] = av.z; As[acol + 3][arow] = av.w;
        Bs[acol + 0][arow] = bv.x; Bs[acol + 1][arow] = bv.y;
        Bs[acol + 2][arow] = bv.z; Bs[acol + 3][arow] = bv.w;
        __syncthreads();

#pragma unroll
        for (int kk = 0; kk < BK; kk++) {
            float a[8], b[8];
            *(float4*)&a[0] = *(const float4*)&As[kk][ty * 8];
            *(float4*)&a[4] = *(const float4*)&As[kk][ty * 8 + 4];
            *(float4*)&b[0] = *(const float4*)&Bs[kk][tx * 8];
            *(float4*)&b[4] = *(const float4*)&Bs[kk][tx * 8 + 4];
#pragma unroll
            for (int i = 0; i < 8; i++)
#pragma unroll
                for (int j = 0; j < 8; j++)
                    acc[i][j] += a[i] * b[j];
        }
        __syncthreads();
    }

#pragma unroll
    for (int i = 0; i < 8; i++) {
        const int m = m0 + ty * 8 + i;
#pragma unroll
        for (int j = 0; j < 8; j++) {
            const int n = n0 + tx * 8 + j;
            float v = acc[i][j];
            if (EPI == EPI_QKV) {
                v = (v + bias[n]) * scale;
                const int r  = m >> 9;      // m / 512
                const int ic = m & 511;     // m % 512
                const int h  = n >> 6;      // n / 64
                const int d  = n & 63;      // n % 64
                Cout[(((size_t)ic * H_ + h) * R_ + r) * D_ + d] = v;
            } else if (EPI == EPI_LOGITS) {
                Cout[((size_t)z * C_ + m) * C_ + n] = v;
            } else { // EPI_OPROJ
                Cout[(size_t)m * E_ + n] = v + bias[n];
            }
        }
    }
}

// ---------------------------------------------------------------------------
// NN variant for context: ctx_h = P_h[512,512] * V_h[512,4096]
// Output scattered to g_ctx[(r*C + i)*E + h*D + d].
// ---------------------------------------------------------------------------
__global__ void __launch_bounds__(256)
gemm_nn_ctx_kernel(const float* __restrict__ P, const float* __restrict__ V,
                   float* __restrict__ Cout)
{
    __shared__ float As[BK][BM];
    __shared__ float Bs[BK][BN];

    const int tid = threadIdx.x;
    const int m0 = blockIdx.y * BM;   // i-tile
    const int n0 = blockIdx.x * BN;   // (r,d)-tile
    const int z  = blockIdx.z;        // head

    const float* A = P + (size_t)z * C_ * C_;   // [i][j], lda = C_
    const float* B = V + (size_t)z * RD;        // [j][(r,d)], ldb = HRD
    const int K = C_;

    const int arow = tid >> 1;
    const int acol = (tid & 1) * 4;
    const float* Ag = A + (size_t)(m0 + arow) * C_ + acol;

    const int krow = tid >> 5;          // 0..7
    const int ncol = (tid & 31) * 4;    // 0..124
    const float* Bg = B + (size_t)krow * HRD + n0 + ncol;

    const int ty = tid >> 4;
    const int tx = tid & 15;

    float acc[8][8];
#pragma unroll
    for (int i = 0; i < 8; i++)
#pragma unroll
        for (int j = 0; j < 8; j++) acc[i][j] = 0.f;

    for (int k0 = 0; k0 < K; k0 += BK) {
        float4 av = *(const float4*)(Ag + k0);
        As[acol + 0][arow] = av.x; As[acol + 1][arow] = av.y;
        As[acol + 2][arow] = av.z; As[acol + 3][arow] = av.w;
        float4 bv = *(const float4*)(Bg + (size_t)k0 * HRD);
        *(float4*)&Bs[krow][ncol] = bv;
        __syncthreads();

#pragma unroll
        for (int kk = 0; kk < BK; kk++) {
            float a[8], b[8];
            *(float4*)&a[0] = *(const float4*)&As[kk][ty * 8];
            *(float4*)&a[4] = *(const float4*)&As[kk][ty * 8 + 4];
            *(float4*)&b[0] = *(const float4*)&Bs[kk][tx * 8];
            *(float4*)&b[4] = *(const float4*)&Bs[kk][tx * 8 + 4];
#pragma unroll
            for (int i = 0; i < 8; i++)
#pragma unroll
                for (int j = 0; j < 8; j++)
                    acc[i][j] += a[i] * b[j];
        }
        __syncthreads();
    }

#pragma unroll
    for (int i = 0; i < 8; i++) {
        const int m = m0 + ty * 8 + i;          // i (column index in C_)
#pragma unroll
        for (int j = 0; j < 8; j++) {
            const int n = n0 + tx * 8 + j;      // (r,d)
            const int r = n >> 6;
            const int d = n & 63;
            Cout[((size_t)(r * C_ + m)) * E_ + z * D_ + d] = acc[i][j];
        }
    }
}

// ---------------------------------------------------------------------------
// Masked softmax over rows of [H*C, C]; writes probs to scratch AND d_out.
// ---------------------------------------------------------------------------
__global__ void __launch_bounds__(512)
softmax_kernel(const float* __restrict__ S, float* __restrict__ P,
               float* __restrict__ Pout)
{
    const int row = blockIdx.x;          // h*C + i
    const int i   = row & (C_ - 1);      // i within head
    const int j   = threadIdx.x;         // 0..511
    const int lane = j & 31;
    const int warp = j >> 5;
    __shared__ float red[16];

    float x = S[(size_t)row * C_ + j];
    if (j == i) x = -1e9f;

    // block max
    float m = x;
#pragma unroll
    for (int o = 16; o > 0; o >>= 1) m = fmaxf(m, __shfl_xor_sync(~0u, m, o));
    if (lane == 0) red[warp] = m;
    __syncthreads();
    if (j < 16) {
        float t = red[j];
#pragma unroll
        for (int o = 8; o > 0; o >>= 1) t = fmaxf(t, __shfl_xor_sync(0xffffu, t, o));
        if (j == 0) red[0] = t;
    }
    __syncthreads();
    const float mx = red[0];
    __syncthreads();

    float e = __expf(x - mx);

    // block sum
    float s = e;
#pragma unroll
    for (int o = 16; o > 0; o >>= 1) s += __shfl_xor_sync(~0u, s, o);
    if (lane == 0) red[warp] = s;
    __syncthreads();
    if (j < 16) {
        float t = red[j];
#pragma unroll
        for (int o = 8; o > 0; o >>= 1) t += __shfl_xor_sync(0xffffu, t, o);
        if (j == 0) red[0] = t;
    }
    __syncthreads();
    const float inv = 1.0f / red[0];

    const float p = e * inv;
    const size_t idx = (size_t)row * C_ + j;
    P[idx] = p;
    Pout[idx] = p;
}

__global__ void copy_l_kernel(const float* __restrict__ l, float* __restrict__ out)
{
    if (threadIdx.x < H_) out[threadIdx.x] = l[threadIdx.x];
}

// ---------------------------------------------------------------------------
// Launch
// ---------------------------------------------------------------------------
extern "C" void kernel_launch(void* const* d_in, const int* in_sizes, int n_in,
                              void* d_out, int out_size)
{
    const float* x  = (const float*)d_in[0];
    // d_in[1] = network (unused by the reference computation)
    const float* Wq = (const float*)d_in[2];
    const float* bq = (const float*)d_in[3];
    const float* Wk = (const float*)d_in[4];
    const float* bk = (const float*)d_in[5];
    const float* Wv = (const float*)d_in[6];
    const float* bv = (const float*)d_in[7];
    const float* Wo = (const float*)d_in[8];
    const float* bo = (const float*)d_in[9];
    const float* l  = (const float*)d_in[10];
    float* out = (float*)d_out;

    float *pQ, *pK, *pV, *pS, *pP, *pCtx;
    cudaGetSymbolAddress((void**)&pQ,   g_Q);
    cudaGetSymbolAddress((void**)&pK,   g_K);
    cudaGetSymbolAddress((void**)&pV,   g_V);
    cudaGetSymbolAddress((void**)&pS,   g_S);
    cudaGetSymbolAddress((void**)&pP,   g_P);
    cudaGetSymbolAddress((void**)&pCtx, g_ctx);

    const dim3 gProj(E_ / BN, M_TOK / BM, 1);     // 6 x 256
    const dim3 gLogits(C_ / BN, C_ / BM, H_);     // 4 x 4 x 12
    const dim3 gCtx(RD / BN, C_ / BM, H_);        // 32 x 4 x 12

    // 1) Q/K/V projections (scatter to [C,H,R,D]; q pre-scaled)
    gemm_nt_kernel<EPI_QKV><<<gProj, 256>>>(x, Wq, bq, pQ, E_, E_, SCALING);
    gemm_nt_kernel<EPI_QKV><<<gProj, 256>>>(x, Wk, bk, pK, E_, E_, 1.0f);
    gemm_nt_kernel<EPI_QKV><<<gProj, 256>>>(x, Wv, bv, pV, E_, E_, 1.0f);

    // 2) tied-row logits: S_h = Q_h * K_h^T over (r,d)
    gemm_nt_kernel<EPI_LOGITS><<<gLogits, 256>>>(pQ, pK, nullptr, pS, HRD, HRD, 1.0f);

    // 3) masked softmax -> probs (scratch + d_out attn_probs section)
    softmax_kernel<<<H_ * C_, 512>>>(pS, pP, out + OUT_OFF_P);

    // 4) context: ctx_h = P_h * V_h, scattered back to [m, E]
    gemm_nn_ctx_kernel<<<gCtx, 256>>>(pP, pV, pCtx);

    // 5) output projection -> d_out
    gemm_nt_kernel<EPI_OPROJ><<<gProj, 256>>>(pCtx, Wo, bo, out, E_, E_, 1.0f);

    // 6) l passthrough
    copy_l_kernel<<<1, 32>>>(l, out + OUT_OFF_L);
}

// round 3
// speedup vs baseline: 3.0458x; 3.0458x over previous
#include <cuda_runtime.h>
#include <cstdint>

// ---------------------------------------------------------------------------
// Problem constants
// ---------------------------------------------------------------------------
constexpr int R_ = 64, C_ = 512, H_ = 12, D_ = 64, E_ = 768;
constexpr int M_TOK = R_ * C_;   // 32768
constexpr int RD    = R_ * D_;   // 4096
constexpr int HRD   = H_ * RD;   // 49152
constexpr long OUT_OFF_P = (long)M_TOK * E_;
constexpr long OUT_OFF_L = OUT_OFF_P + (long)H_ * C_ * C_;
constexpr float SCALING = 0.015625f;  // D^-0.5 / sqrt(R)

// ---------------------------------------------------------------------------
// Scratch (static __device__ arrays)
// ---------------------------------------------------------------------------
__device__ float g_xt[(size_t)M_TOK * E_];     // tf32-rounded x
__device__ float g_Wt[4 * (size_t)E_ * E_];    // tf32-rounded Wq,Wk,Wv,Wo
__device__ float g_Q [(size_t)C_ * HRD];       // [i][h][r][d] (rounded)
__device__ float g_K [(size_t)C_ * HRD];       // [i][h][r][d] (rounded)
__device__ float g_Vt[(size_t)H_ * RD * C_];   // [h][r*D+d][i] (rounded)
__device__ float g_S [(size_t)H_ * C_ * C_];   // logits (full fp32)
__device__ float g_P [(size_t)H_ * C_ * C_];   // probs (rounded, feeds ctx)
__device__ float g_ctx[(size_t)M_TOK * E_];    // [m][e] (rounded)

// ---------------------------------------------------------------------------
// Helpers
// ---------------------------------------------------------------------------
__device__ __forceinline__ float tf32r(float f) {
    uint32_t r;
    asm("cvt.rna.tf32.f32 %0, %1;" : "=r"(r) : "f"(f));
    return __uint_as_float(r);
}
__device__ __forceinline__ uint32_t smem_u32(const void* p) {
    uint32_t a;
    asm("{ .reg .u64 t; cvta.to.shared.u64 t, %1; cvt.u32.u64 %0, t; }"
        : "=r"(a) : "l"(p));
    return a;
}
__device__ __forceinline__ void cpa16(uint32_t dst, const void* src) {
    asm volatile("cp.async.cg.shared.global [%0], [%1], 16;"
                 :: "r"(dst), "l"(src) : "memory");
}

// elementwise tf32 rounding pre-pass (float4)
__global__ void __launch_bounds__(256)
round_kernel(const float* __restrict__ in, float* __restrict__ out, int n4) {
    int i = blockIdx.x * blockDim.x + threadIdx.x;
    if (i < n4) {
        float4 v = ((const float4*)in)[i];
        v.x = tf32r(v.x); v.y = tf32r(v.y);
        v.z = tf32r(v.z); v.w = tf32r(v.w);
        ((float4*)out)[i] = v;
    }
}

// ---------------------------------------------------------------------------
// tf32 mma.sync GEMM:  Cout = epi( A[M,K] * B[N,K]^T )
// Block 256x128x16, 256 threads (8 warps as 4m x 2n), warp tile 64x64.
// ---------------------------------------------------------------------------
constexpr int BM = 256, BN = 128, BK = 16;
constexpr int AS_STRIDE = 20;                      // floats per A smem row
constexpr int BS_STRIDE = 20;
constexpr int AS_FLOATS = BM * AS_STRIDE;          // 5120
constexpr int BS_FLOATS = BN * BS_STRIDE;          // 2560
constexpr int STAGE_FLOATS = AS_FLOATS + BS_FLOATS;
constexpr int SMEM_BYTES = 2 * STAGE_FLOATS * 4;   // 61440

enum { EPI_QKV = 0, EPI_VT = 1, EPI_LOGITS = 2, EPI_CTX = 3, EPI_OPROJ = 4 };

template <int EPI>
__global__ void __launch_bounds__(256, 1)
mm_kernel(const float* __restrict__ A, const float* __restrict__ B,
          const float* __restrict__ bias, float* __restrict__ Cout,
          int lda, int ldb, int K, float scale)
{
    extern __shared__ float sm[];
    const int tid = threadIdx.x;
    const int wid = tid >> 5, lane = tid & 31;
    const int m0 = blockIdx.y * BM;
    const int n0 = blockIdx.x * BN;
    const int z  = blockIdx.z;

    if (EPI == EPI_LOGITS) { A += (size_t)z * RD;      B += (size_t)z * RD; }
    if (EPI == EPI_CTX)    { A += (size_t)z * C_ * C_; B += (size_t)z * RD * C_; }

    const uint32_t smb = smem_u32(sm);

    const int warp_m = wid >> 1;          // 0..3
    const int warp_n = wid & 1;           // 0..1
    const int mb_base = warp_m * 64;
    const int nb_base = warp_n * 64;
    const int r4 = lane >> 2, c4 = lane & 3;

    float acc[4][8][4];
#pragma unroll
    for (int a = 0; a < 4; a++)
#pragma unroll
        for (int b = 0; b < 8; b++)
#pragma unroll
            for (int c = 0; c < 4; c++) acc[a][b][c] = 0.f;

    const int NC = K / BK;

    // ---- async stage loader
    auto load_stage = [&](int c, int s) {
        const float* Ab = A + (size_t)m0 * lda + c * BK;
        const float* Bb = B + (size_t)n0 * ldb + c * BK;
        const uint32_t asb = smb + (uint32_t)(s * STAGE_FLOATS) * 4u;
        const uint32_t bsb = asb + AS_FLOATS * 4u;
#pragma unroll
        for (int i = 0; i < 4; i++) {          // A: 256 rows x 16k = 1024 f4
            int q = i * 256 + tid;
            int row = q >> 2, kq = q & 3;
            cpa16(asb + (uint32_t)(row * AS_STRIDE + kq * 4) * 4u,
                  Ab + (size_t)row * lda + kq * 4);
        }
#pragma unroll
        for (int i = 0; i < 2; i++) {          // B: 128 rows x 16k = 512 f4
            int q = i * 256 + tid;
            int row = q >> 2, kq = q & 3;
            cpa16(bsb + (uint32_t)(row * BS_STRIDE + kq * 4) * 4u,
                  Bb + (size_t)row * ldb + kq * 4);
        }
        asm volatile("cp.async.commit_group;" ::: "memory");
    };

    load_stage(0, 0);

    for (int c = 0; c < NC; c++) {
        const int s = c & 1;
        if (c + 1 < NC) {
            load_stage(c + 1, (c + 1) & 1);
            asm volatile("cp.async.wait_group 1;" ::: "memory");
        } else {
            asm volatile("cp.async.wait_group 0;" ::: "memory");
        }
        __syncthreads();

        const float* As = sm + s * STAGE_FLOATS;
        const float* Bs = As + AS_FLOATS;

#pragma unroll
        for (int ks = 0; ks < BK; ks += 8) {
            uint32_t afr[4][4], bfr[8][2];
#pragma unroll
            for (int mb = 0; mb < 4; mb++) {
                const float* ap = As + (mb_base + mb * 16 + r4) * AS_STRIDE + ks + c4;
                afr[mb][0] = __float_as_uint(ap[0]);
                afr[mb][1] = __float_as_uint(ap[8 * AS_STRIDE]);
                afr[mb][2] = __float_as_uint(ap[4]);
                afr[mb][3] = __float_as_uint(ap[8 * AS_STRIDE + 4]);
            }
#pragma unroll
            for (int nb = 0; nb < 8; nb++) {
                const float* bp = Bs + (nb_base + nb * 8 + r4) * BS_STRIDE + ks + c4;
                bfr[nb][0] = __float_as_uint(bp[0]);
                bfr[nb][1] = __float_as_uint(bp[4]);
            }
#pragma unroll
            for (int mb = 0; mb < 4; mb++)
#pragma unroll
                for (int nb = 0; nb < 8; nb++) {
                    asm volatile(
                        "mma.sync.aligned.m16n8k8.row.col.f32.tf32.tf32.f32 "
                        "{%0,%1,%2,%3}, {%4,%5,%6,%7}, {%8,%9}, {%0,%1,%2,%3};"
                        : "+f"(acc[mb][nb][0]), "+f"(acc[mb][nb][1]),
                          "+f"(acc[mb][nb][2]), "+f"(acc[mb][nb][3])
                        : "r"(afr[mb][0]), "r"(afr[mb][1]),
                          "r"(afr[mb][2]), "r"(afr[mb][3]),
                          "r"(bfr[nb][0]), "r"(bfr[nb][1]));
                }
        }
        __syncthreads();
    }

    // ---- epilogue
#pragma unroll
    for (int mb = 0; mb < 4; mb++) {
#pragma unroll
        for (int half = 0; half < 2; half++) {
            const int m = m0 + mb_base + mb * 16 + r4 + half * 8;
#pragma unroll
            for (int nb = 0; nb < 8; nb++) {
                const int n = n0 + nb_base + nb * 8 + c4 * 2;
                float v0 = acc[mb][nb][half * 2 + 0];
                float v1 = acc[mb][nb][half * 2 + 1];

                if (EPI == EPI_QKV) {
                    v0 = tf32r((v0 + bias[n])     * scale);
                    v1 = tf32r((v1 + bias[n + 1]) * scale);
                    const int r = m >> 9, ic = m & 511;
                    const int h = n >> 6, d = n & 63;
                    float2* dst = (float2*)(Cout +
                        (((size_t)ic * H_ + h) * R_ + r) * D_ + d);
                    *dst = make_float2(v0, v1);
                } else if (EPI == EPI_VT) {
                    v0 = tf32r(v0 + bias[n]);
                    v1 = tf32r(v1 + bias[n + 1]);
                    const int r = m >> 9, ic = m & 511;
                    const int h = n >> 6, d = n & 63;
                    float* dst = Cout + ((size_t)h * RD + r * D_ + d) * C_ + ic;
                    dst[0]  = v0;
                    dst[C_] = v1;
                } else if (EPI == EPI_LOGITS) {
                    float2* dst = (float2*)(Cout + ((size_t)z * C_ + m) * C_ + n);
                    *dst = make_float2(v0, v1);
                } else if (EPI == EPI_CTX) {
                    const int r = n >> 6, d = n & 63;
                    float2* dst = (float2*)(Cout +
                        ((size_t)(r * C_) + m) * E_ + z * D_ + d);
                    *dst = make_float2(tf32r(v0), tf32r(v1));
                } else { // EPI_OPROJ
                    float2* dst = (float2*)(Cout + (size_t)m * E_ + n);
                    *dst = make_float2(v0 + bias[n], v1 + bias[n + 1]);
                }
            }
        }
    }
}

// ---------------------------------------------------------------------------
// Masked softmax over rows of [H*C, C]; full fp32 to d_out, tf32-rounded to P.
// ---------------------------------------------------------------------------
__global__ void __launch_bounds__(512)
softmax_kernel(const float* __restrict__ S, float* __restrict__ P,
               float* __restrict__ Pout)
{
    const int row = blockIdx.x;
    const int i   = row & (C_ - 1);
    const int j   = threadIdx.x;
    const int lane = j & 31, warp = j >> 5;
    __shared__ float red[16];

    float x = S[(size_t)row * C_ + j];
    if (j == i) x = -1e9f;

    float m = x;
#pragma unroll
    for (int o = 16; o > 0; o >>= 1) m = fmaxf(m, __shfl_xor_sync(~0u, m, o));
    if (lane == 0) red[warp] = m;
    __syncthreads();
    if (j < 16) {
        float t = red[j];
#pragma unroll
        for (int o = 8; o > 0; o >>= 1) t = fmaxf(t, __shfl_xor_sync(0xffffu, t, o));
        if (j == 0) red[0] = t;
    }
    __syncthreads();
    const float mx = red[0];
    __syncthreads();

    float e = __expf(x - mx);
    float sacc = e;
#pragma unroll
    for (int o = 16; o > 0; o >>= 1) sacc += __shfl_xor_sync(~0u, sacc, o);
    if (lane == 0) red[warp] = sacc;
    __syncthreads();
    if (j < 16) {
        float t = red[j];
#pragma unroll
        for (int o = 8; o > 0; o >>= 1) t += __shfl_xor_sync(0xffffu, t, o);
        if (j == 0) red[0] = t;
    }
    __syncthreads();
    const float inv = 1.0f / red[0];

    const float p = e * inv;
    const size_t idx = (size_t)row * C_ + j;
    P[idx]    = tf32r(p);
    Pout[idx] = p;
}

__global__ void copy_l_kernel(const float* __restrict__ l, float* __restrict__ out)
{
    if (threadIdx.x < H_) out[threadIdx.x] = l[threadIdx.x];
}

// ---------------------------------------------------------------------------
// Launch
// ---------------------------------------------------------------------------
extern "C" void kernel_launch(void* const* d_in, const int* in_sizes, int n_in,
                              void* d_out, int out_size)
{
    const float* x  = (const float*)d_in[0];
    const float* Wq = (const float*)d_in[2];
    const float* bq = (const float*)d_in[3];
    const float* Wk = (const float*)d_in[4];
    const float* bk = (const float*)d_in[5];
    const float* Wv = (const float*)d_in[6];
    const float* bv = (const float*)d_in[7];
    const float* Wo = (const float*)d_in[8];
    const float* bo = (const float*)d_in[9];
    const float* l  = (const float*)d_in[10];
    float* out = (float*)d_out;

    float *pXt, *pWt, *pQ, *pK, *pVt, *pS, *pP, *pCtx;
    cudaGetSymbolAddress((void**)&pXt,  g_xt);
    cudaGetSymbolAddress((void**)&pWt,  g_Wt);
    cudaGetSymbolAddress((void**)&pQ,   g_Q);
    cudaGetSymbolAddress((void**)&pK,   g_K);
    cudaGetSymbolAddress((void**)&pVt,  g_Vt);
    cudaGetSymbolAddress((void**)&pS,   g_S);
    cudaGetSymbolAddress((void**)&pP,   g_P);
    cudaGetSymbolAddress((void**)&pCtx, g_ctx);

    cudaFuncSetAttribute(mm_kernel<EPI_QKV>,    cudaFuncAttributeMaxDynamicSharedMemorySize, SMEM_BYTES);
    cudaFuncSetAttribute(mm_kernel<EPI_VT>,     cudaFuncAttributeMaxDynamicSharedMemorySize, SMEM_BYTES);
    cudaFuncSetAttribute(mm_kernel<EPI_LOGITS>, cudaFuncAttributeMaxDynamicSharedMemorySize, SMEM_BYTES);
    cudaFuncSetAttribute(mm_kernel<EPI_CTX>,    cudaFuncAttributeMaxDynamicSharedMemorySize, SMEM_BYTES);
    cudaFuncSetAttribute(mm_kernel<EPI_OPROJ>,  cudaFuncAttributeMaxDynamicSharedMemorySize, SMEM_BYTES);

    const size_t WSZ = (size_t)E_ * E_;

    // 0) tf32 pre-rounding of raw inputs
    {
        int n4x = (int)((size_t)M_TOK * E_ / 4);
        round_kernel<<<(n4x + 255) / 256, 256>>>(x, pXt, n4x);
        int n4w = (int)(WSZ / 4);
        round_kernel<<<(n4w + 255) / 256, 256>>>(Wq, pWt + 0 * WSZ, n4w);
        round_kernel<<<(n4w + 255) / 256, 256>>>(Wk, pWt + 1 * WSZ, n4w);
        round_kernel<<<(n4w + 255) / 256, 256>>>(Wv, pWt + 2 * WSZ, n4w);
        round_kernel<<<(n4w + 255) / 256, 256>>>(Wo, pWt + 3 * WSZ, n4w);
    }

    const dim3 gProj(E_ / BN, M_TOK / BM, 1);   // 6 x 128
    const dim3 gLog (C_ / BN, C_ / BM, H_);     // 4 x 2 x 12
    const dim3 gCtx (RD / BN, C_ / BM, H_);     // 32 x 2 x 12

    // 1) projections (Q pre-scaled; V written transposed)
    mm_kernel<EPI_QKV><<<gProj, 256, SMEM_BYTES>>>(pXt, pWt + 0 * WSZ, bq, pQ,  E_, E_, E_, SCALING);
    mm_kernel<EPI_QKV><<<gProj, 256, SMEM_BYTES>>>(pXt, pWt + 1 * WSZ, bk, pK,  E_, E_, E_, 1.0f);
    mm_kernel<EPI_VT ><<<gProj, 256, SMEM_BYTES>>>(pXt, pWt + 2 * WSZ, bv, pVt, E_, E_, E_, 1.0f);

    // 2) tied-row logits: S_h = Q_h * K_h^T  (K = 4096)
    mm_kernel<EPI_LOGITS><<<gLog, 256, SMEM_BYTES>>>(pQ, pK, nullptr, pS, HRD, HRD, RD, 1.0f);

    // 3) masked softmax
    softmax_kernel<<<H_ * C_, 512>>>(pS, pP, out + OUT_OFF_P);

    // 4) context: Ctx_h = P_h * Vt_h^T  (K = 512)
    mm_kernel<EPI_CTX><<<gCtx, 256, SMEM_BYTES>>>(pP, pVt, nullptr, pCtx, C_, C_, C_, 1.0f);

    // 5) output projection
    mm_kernel<EPI_OPROJ><<<gProj, 256, SMEM_BYTES>>>(pCtx, pWt + 3 * WSZ, bo, out, E_, E_, E_, 1.0f);

    // 6) l passthrough
    copy_l_kernel<<<1, 32>>>(l, out + OUT_OFF_L);
}

// round 4
// speedup vs baseline: 3.1427x; 1.0318x over previous
#include <cuda_runtime.h>
#include <cstdint>

// ---------------------------------------------------------------------------
// Problem constants
// ---------------------------------------------------------------------------
constexpr int R_ = 64, C_ = 512, H_ = 12, D_ = 64, E_ = 768;
constexpr int M_TOK = R_ * C_;   // 32768
constexpr int RD    = R_ * D_;   // 4096
constexpr int HRD   = H_ * RD;   // 49152
constexpr long OUT_OFF_P = (long)M_TOK * E_;
constexpr long OUT_OFF_L = OUT_OFF_P + (long)H_ * C_ * C_;
constexpr float SCALING = 0.015625f;  // D^-0.5 / sqrt(R)

// ---------------------------------------------------------------------------
// Scratch (static __device__ arrays)
// ---------------------------------------------------------------------------
__device__ float g_xt[(size_t)M_TOK * E_];     // tf32-rounded x
__device__ float g_Wt[4 * (size_t)E_ * E_];    // tf32-rounded Wq,Wk,Wv,Wo
__device__ float g_Q [(size_t)C_ * HRD];       // [i][h][r][d] (rounded)
__device__ float g_K [(size_t)C_ * HRD];       // [i][h][r][d] (rounded)
__device__ float g_Vt[(size_t)H_ * RD * C_];   // [h][r*D+d][i] (rounded)
__device__ float g_S [(size_t)H_ * C_ * C_];   // logits (full fp32)
__device__ float g_P [(size_t)H_ * C_ * C_];   // probs (rounded)
__device__ float g_ctx[(size_t)M_TOK * E_];    // [m][e] (rounded)

// ---------------------------------------------------------------------------
// Helpers
// ---------------------------------------------------------------------------
__device__ __forceinline__ float tf32r(float f) {
    uint32_t r;
    asm("cvt.rna.tf32.f32 %0, %1;" : "=r"(r) : "f"(f));
    return __uint_as_float(r);
}
__device__ __forceinline__ uint32_t smem_u32(const void* p) {
    uint32_t a;
    asm("{ .reg .u64 t; cvta.to.shared.u64 t, %1; cvt.u32.u64 %0, t; }"
        : "=r"(a) : "l"(p));
    return a;
}
__device__ __forceinline__ void cpa16(uint32_t dst, const void* src) {
    asm volatile("cp.async.cg.shared.global [%0], [%1], 16;"
                 :: "r"(dst), "l"(src) : "memory");
}
__device__ __forceinline__ void ldsm4(uint32_t& r0, uint32_t& r1,
                                      uint32_t& r2, uint32_t& r3, uint32_t addr) {
    asm volatile("ldmatrix.sync.aligned.m8n8.x4.shared.b16 {%0,%1,%2,%3}, [%4];"
                 : "=r"(r0), "=r"(r1), "=r"(r2), "=r"(r3) : "r"(addr));
}

// elementwise tf32 rounding pre-pass (float4)
__global__ void __launch_bounds__(256)
round_kernel(const float* __restrict__ in, float* __restrict__ out, int n4) {
    int i = blockIdx.x * blockDim.x + threadIdx.x;
    if (i < n4) {
        float4 v = ((const float4*)in)[i];
        v.x = tf32r(v.x); v.y = tf32r(v.y);
        v.z = tf32r(v.z); v.w = tf32r(v.w);
        ((float4*)out)[i] = v;
    }
}

// ---------------------------------------------------------------------------
// tf32 mma.sync GEMM:  Cout = epi( A[M,K] * B[N,K]^T )
// Block 256x128x16, 256 threads (8 warps as 4m x 2n), warp tile 64x64.
// 5-stage cp.async pipeline; ldmatrix fragment loads.
// ---------------------------------------------------------------------------
constexpr int BM = 256, BN = 128, BK = 16;
constexpr int STAGES = 5;
constexpr int AS_STRIDE = 20;                      // floats per smem row (80B)
constexpr int BS_STRIDE = 20;
constexpr int AS_FLOATS = BM * AS_STRIDE;          // 5120
constexpr int BS_FLOATS = BN * BS_STRIDE;          // 2560
constexpr int STAGE_FLOATS = AS_FLOATS + BS_FLOATS;   // 7680
constexpr int SMEM_BYTES = STAGES * STAGE_FLOATS * 4; // 153600

enum { EPI_QKV = 0, EPI_VT = 1, EPI_LOGITS = 2, EPI_CTX = 3, EPI_OPROJ = 4 };

template <int EPI>
__global__ void __launch_bounds__(256, 1)
mm_kernel(const float* __restrict__ A, const float* __restrict__ B,
          const float* __restrict__ bias, float* __restrict__ Cout,
          int lda, int ldb, int K, float scale)
{
    extern __shared__ float sm[];
    const int tid = threadIdx.x;
    const int wid = tid >> 5, lane = tid & 31;
    const int m0 = blockIdx.y * BM;
    const int n0 = blockIdx.x * BN;
    const int z  = blockIdx.z;

    if (EPI == EPI_LOGITS) { A += (size_t)z * RD;      B += (size_t)z * RD; }
    if (EPI == EPI_CTX)    { A += (size_t)z * C_ * C_; B += (size_t)z * RD * C_; }

    const uint32_t smb = smem_u32(sm);

    const int warp_m = wid >> 1;          // 0..3
    const int warp_n = wid & 1;           // 0..1
    const int mb_base = warp_m * 64;
    const int nb_base = warp_n * 64;
    const int r4 = lane >> 2, c4 = lane & 3;

    // ldmatrix per-lane offsets (bytes, relative to stage base)
    // A tile (16x8 per x4): threads 0-15 -> rows lane&15 (k low), 16-31 -> k+4
    const uint32_t a_off =
        (uint32_t)(((mb_base + (lane & 15)) * AS_STRIDE + ((lane >> 4) << 2)) * 4);
    // B pair (two 8x8 n-tiles): t0-7 n rows, klow; t8-15 khigh; t16-23 rows+8 klow; t24-31 khigh
    const uint32_t b_off =
        (uint32_t)(((nb_base + (lane & 7) + ((lane & 16) >> 1)) * BS_STRIDE +
                    (((lane >> 3) & 1) << 2)) * 4);

    float acc[4][8][4];
#pragma unroll
    for (int a = 0; a < 4; a++)
#pragma unroll
        for (int b = 0; b < 8; b++)
#pragma unroll
            for (int c = 0; c < 4; c++) acc[a][b][c] = 0.f;

    const int NC = K / BK;

    auto load_stage = [&](int c, int s) {
        const float* Ab = A + (size_t)m0 * lda + c * BK;
        const float* Bb = B + (size_t)n0 * ldb + c * BK;
        const uint32_t asb = smb + (uint32_t)(s * STAGE_FLOATS) * 4u;
        const uint32_t bsb = asb + AS_FLOATS * 4u;
#pragma unroll
        for (int i = 0; i < 4; i++) {          // A: 256 rows x 16k = 1024 f4
            int q = i * 256 + tid;
            int row = q >> 2, kq = q & 3;
            cpa16(asb + (uint32_t)(row * AS_STRIDE + kq * 4) * 4u,
                  Ab + (size_t)row * lda + kq * 4);
        }
#pragma unroll
        for (int i = 0; i < 2; i++) {          // B: 128 rows x 16k = 512 f4
            int q = i * 256 + tid;
            int row = q >> 2, kq = q & 3;
            cpa16(bsb + (uint32_t)(row * BS_STRIDE + kq * 4) * 4u,
                  Bb + (size_t)row * ldb + kq * 4);
        }
        asm volatile("cp.async.commit_group;" ::: "memory");
    };

    // prologue: fill STAGES-1 buffers
#pragma unroll
    for (int s = 0; s < STAGES - 1; s++)
        if (s < NC) load_stage(s, s);

    int sidx = 0;
    for (int c = 0; c < NC; c++) {
        asm volatile("cp.async.wait_group %0;" :: "n"(STAGES - 2) : "memory");
        __syncthreads();

        // prefetch chunk c+STAGES-1 into the buffer freed last iteration
        const int cn = c + STAGES - 1;
        if (cn < NC) {
            int sn = sidx + STAGES - 1; if (sn >= STAGES) sn -= STAGES;
            load_stage(cn, sn);
        }

        const uint32_t abase = smb + (uint32_t)(sidx * STAGE_FLOATS) * 4u + a_off;
        const uint32_t bbase = smb + (uint32_t)(sidx * STAGE_FLOATS + AS_FLOATS) * 4u + b_off;

#pragma unroll
        for (int ks = 0; ks < BK; ks += 8) {
            uint32_t afr[4][4], bfr[8][2];
#pragma unroll
            for (int mb = 0; mb < 4; mb++)
                ldsm4(afr[mb][0], afr[mb][1], afr[mb][2], afr[mb][3],
                      abase + (uint32_t)((mb * 16 * AS_STRIDE + ks) * 4));
#pragma unroll
            for (int p = 0; p < 4; p++)
                ldsm4(bfr[2*p][0], bfr[2*p][1], bfr[2*p+1][0], bfr[2*p+1][1],
                      bbase + (uint32_t)((p * 16 * BS_STRIDE + ks) * 4));
#pragma unroll
            for (int mb = 0; mb < 4; mb++)
#pragma unroll
                for (int nb = 0; nb < 8; nb++) {
                    asm volatile(
                        "mma.sync.aligned.m16n8k8.row.col.f32.tf32.tf32.f32 "
                        "{%0,%1,%2,%3}, {%4,%5,%6,%7}, {%8,%9}, {%0,%1,%2,%3};"
                        : "+f"(acc[mb][nb][0]), "+f"(acc[mb][nb][1]),
                          "+f"(acc[mb][nb][2]), "+f"(acc[mb][nb][3])
                        : "r"(afr[mb][0]), "r"(afr[mb][1]),
                          "r"(afr[mb][2]), "r"(afr[mb][3]),
                          "r"(bfr[nb][0]), "r"(bfr[nb][1]));
                }
        }
        if (++sidx == STAGES) sidx = 0;
    }

    // ---- epilogue
#pragma unroll
    for (int mb = 0; mb < 4; mb++) {
#pragma unroll
        for (int half = 0; half < 2; half++) {
            const int m = m0 + mb_base + mb * 16 + r4 + half * 8;
#pragma unroll
            for (int nb = 0; nb < 8; nb++) {
                const int n = n0 + nb_base + nb * 8 + c4 * 2;
                float v0 = acc[mb][nb][half * 2 + 0];
                float v1 = acc[mb][nb][half * 2 + 1];

                if (EPI == EPI_QKV) {
                    v0 = tf32r((v0 + bias[n])     * scale);
                    v1 = tf32r((v1 + bias[n + 1]) * scale);
                    const int r = m >> 9, ic = m & 511;
                    const int h = n >> 6, d = n & 63;
                    float2* dst = (float2*)(Cout +
                        (((size_t)ic * H_ + h) * R_ + r) * D_ + d);
                    *dst = make_float2(v0, v1);
                } else if (EPI == EPI_VT) {
                    v0 = tf32r(v0 + bias[n]);
                    v1 = tf32r(v1 + bias[n + 1]);
                    const int r = m >> 9, ic = m & 511;
                    const int h = n >> 6, d = n & 63;
                    float* dst = Cout + ((size_t)h * RD + r * D_ + d) * C_ + ic;
                    dst[0]  = v0;
                    dst[C_] = v1;
                } else if (EPI == EPI_LOGITS) {
                    float2* dst = (float2*)(Cout + ((size_t)z * C_ + m) * C_ + n);
                    *dst = make_float2(v0, v1);
                } else if (EPI == EPI_CTX) {
                    const int r = n >> 6, d = n & 63;
                    float2* dst = (float2*)(Cout +
                        ((size_t)(r * C_) + m) * E_ + z * D_ + d);
                    *dst = make_float2(tf32r(v0), tf32r(v1));
                } else { // EPI_OPROJ
                    float2* dst = (float2*)(Cout + (size_t)m * E_ + n);
                    *dst = make_float2(v0 + bias[n], v1 + bias[n + 1]);
                }
            }
        }
    }
}

// ---------------------------------------------------------------------------
// Masked softmax over rows of [H*C, C]; full fp32 to d_out, rounded to P.
// ---------------------------------------------------------------------------
__global__ void __launch_bounds__(512)
softmax_kernel(const float* __restrict__ S, float* __restrict__ P,
               float* __restrict__ Pout)
{
    const int row = blockIdx.x;
    const int i   = row & (C_ - 1);
    const int j   = threadIdx.x;
    const int lane = j & 31, warp = j >> 5;
    __shared__ float red[16];

    float x = S[(size_t)row * C_ + j];
    if (j == i) x = -1e9f;

    float m = x;
#pragma unroll
    for (int o = 16; o > 0; o >>= 1) m = fmaxf(m, __shfl_xor_sync(~0u, m, o));
    if (lane == 0) red[warp] = m;
    __syncthreads();
    if (j < 16) {
        float t = red[j];
#pragma unroll
        for (int o = 8; o > 0; o >>= 1) t = fmaxf(t, __shfl_xor_sync(0xffffu, t, o));
        if (j == 0) red[0] = t;
    }
    __syncthreads();
    const float mx = red[0];
    __syncthreads();

    float e = __expf(x - mx);
    float sacc = e;
#pragma unroll
    for (int o = 16; o > 0; o >>= 1) sacc += __shfl_xor_sync(~0u, sacc, o);
    if (lane == 0) red[warp] = sacc;
    __syncthreads();
    if (j < 16) {
        float t = red[j];
#pragma unroll
        for (int o = 8; o > 0; o >>= 1) t += __shfl_xor_sync(0xffffu, t, o);
        if (j == 0) red[0] = t;
    }
    __syncthreads();
    const float inv = 1.0f / red[0];

    const float p = e * inv;
    const size_t idx = (size_t)row * C_ + j;
    P[idx]    = tf32r(p);
    Pout[idx] = p;
}

__global__ void copy_l_kernel(const float* __restrict__ l, float* __restrict__ out)
{
    if (threadIdx.x < H_) out[threadIdx.x] = l[threadIdx.x];
}

// ---------------------------------------------------------------------------
// Launch
// ---------------------------------------------------------------------------
extern "C" void kernel_launch(void* const* d_in, const int* in_sizes, int n_in,
                              void* d_out, int out_size)
{
    const float* x  = (const float*)d_in[0];
    const float* Wq = (const float*)d_in[2];
    const float* bq = (const float*)d_in[3];
    const float* Wk = (const float*)d_in[4];
    const float* bk = (const float*)d_in[5];
    const float* Wv = (const float*)d_in[6];
    const float* bv = (const float*)d_in[7];
    const float* Wo = (const float*)d_in[8];
    const float* bo = (const float*)d_in[9];
    const float* l  = (const float*)d_in[10];
    float* out = (float*)d_out;

    float *pXt, *pWt, *pQ, *pK, *pVt, *pS, *pP, *pCtx;
    cudaGetSymbolAddress((void**)&pXt,  g_xt);
    cudaGetSymbolAddress((void**)&pWt,  g_Wt);
    cudaGetSymbolAddress((void**)&pQ,   g_Q);
    cudaGetSymbolAddress((void**)&pK,   g_K);
    cudaGetSymbolAddress((void**)&pVt,  g_Vt);
    cudaGetSymbolAddress((void**)&pS,   g_S);
    cudaGetSymbolAddress((void**)&pP,   g_P);
    cudaGetSymbolAddress((void**)&pCtx, g_ctx);

    cudaFuncSetAttribute(mm_kernel<EPI_QKV>,    cudaFuncAttributeMaxDynamicSharedMemorySize, SMEM_BYTES);
    cudaFuncSetAttribute(mm_kernel<EPI_VT>,     cudaFuncAttributeMaxDynamicSharedMemorySize, SMEM_BYTES);
    cudaFuncSetAttribute(mm_kernel<EPI_LOGITS>, cudaFuncAttributeMaxDynamicSharedMemorySize, SMEM_BYTES);
    cudaFuncSetAttribute(mm_kernel<EPI_CTX>,    cudaFuncAttributeMaxDynamicSharedMemorySize, SMEM_BYTES);
    cudaFuncSetAttribute(mm_kernel<EPI_OPROJ>,  cudaFuncAttributeMaxDynamicSharedMemorySize, SMEM_BYTES);

    const size_t WSZ = (size_t)E_ * E_;

    // 0) tf32 pre-rounding of raw inputs
    {
        int n4x = (int)((size_t)M_TOK * E_ / 4);
        round_kernel<<<(n4x + 255) / 256, 256>>>(x, pXt, n4x);
        int n4w = (int)(WSZ / 4);
        round_kernel<<<(n4w + 255) / 256, 256>>>(Wq, pWt + 0 * WSZ, n4w);
        round_kernel<<<(n4w + 255) / 256, 256>>>(Wk, pWt + 1 * WSZ, n4w);
        round_kernel<<<(n4w + 255) / 256, 256>>>(Wv, pWt + 2 * WSZ, n4w);
        round_kernel<<<(n4w + 255) / 256, 256>>>(Wo, pWt + 3 * WSZ, n4w);
    }

    const dim3 gProj(E_ / BN, M_TOK / BM, 1);   // 6 x 128
    const dim3 gLog (C_ / BN, C_ / BM, H_);     // 4 x 2 x 12
    const dim3 gCtx (RD / BN, C_ / BM, H_);     // 32 x 2 x 12

    // 1) projections (Q pre-scaled; V written transposed)
    mm_kernel<EPI_QKV><<<gProj, 256, SMEM_BYTES>>>(pXt, pWt + 0 * WSZ, bq, pQ,  E_, E_, E_, SCALING);
    mm_kernel<EPI_QKV><<<gProj, 256, SMEM_BYTES>>>(pXt, pWt + 1 * WSZ, bk, pK,  E_, E_, E_, 1.0f);
    mm_kernel<EPI_VT ><<<gProj, 256, SMEM_BYTES>>>(pXt, pWt + 2 * WSZ, bv, pVt, E_, E_, E_, 1.0f);

    // 2) tied-row logits: S_h = Q_h * K_h^T  (K = 4096)
    mm_kernel<EPI_LOGITS><<<gLog, 256, SMEM_BYTES>>>(pQ, pK, nullptr, pS, HRD, HRD, RD, 1.0f);

    // 3) masked softmax
    softmax_kernel<<<H_ * C_, 512>>>(pS, pP, out + OUT_OFF_P);

    // 4) context: Ctx_h = P_h * Vt_h^T  (K = 512)
    mm_kernel<EPI_CTX><<<gCtx, 256, SMEM_BYTES>>>(pP, pVt, nullptr, pCtx, C_, C_, C_, 1.0f);

    // 5) output projection
    mm_kernel<EPI_OPROJ><<<gProj, 256, SMEM_BYTES>>>(pCtx, pWt + 3 * WSZ, bo, out, E_, E_, E_, 1.0f);

    // 6) l passthrough
    copy_l_kernel<<<1, 32>>>(l, out + OUT_OFF_L);
}

// round 5
// speedup vs baseline: 5.9456x; 1.8919x over previous
#include <cuda_runtime.h>
#include <cuda_fp16.h>
#include <cstdint>

// ---------------------------------------------------------------------------
// Problem constants
// ---------------------------------------------------------------------------
constexpr int R_ = 64, C_ = 512, H_ = 12, D_ = 64, E_ = 768;
constexpr int M_TOK = R_ * C_;   // 32768
constexpr int RD    = R_ * D_;   // 4096
constexpr int HRD   = H_ * RD;   // 49152
constexpr long OUT_OFF_P = (long)M_TOK * E_;
constexpr long OUT_OFF_L = OUT_OFF_P + (long)H_ * C_ * C_;
constexpr float SCALING = 0.015625f;  // D^-0.5 / sqrt(R)

// ---------------------------------------------------------------------------
// Scratch (static __device__ arrays) — fp16 operands, fp32 logits
// ---------------------------------------------------------------------------
__device__ __half g_xh [(size_t)M_TOK * E_];     // x in fp16
__device__ __half g_Wh [4 * (size_t)E_ * E_];    // Wq,Wk,Wv,Wo fp16
__device__ __half g_Q  [(size_t)C_ * HRD];       // [i][h][r][d]
__device__ __half g_K  [(size_t)C_ * HRD];       // [i][h][r][d]
__device__ __half g_Vt [(size_t)H_ * RD * C_];   // [h][r*D+d][i]
__device__ float  g_S  [(size_t)H_ * C_ * C_];   // logits fp32
__device__ __half g_P  [(size_t)H_ * C_ * C_];   // probs fp16
__device__ __half g_ctx[(size_t)M_TOK * E_];     // [m][e]

// ---------------------------------------------------------------------------
// Helpers
// ---------------------------------------------------------------------------
__device__ __forceinline__ uint32_t smem_u32(const void* p) {
    uint32_t a;
    asm("{ .reg .u64 t; cvta.to.shared.u64 t, %1; cvt.u32.u64 %0, t; }"
        : "=r"(a) : "l"(p));
    return a;
}
__device__ __forceinline__ void cpa16(uint32_t dst, const void* src) {
    asm volatile("cp.async.cg.shared.global [%0], [%1], 16;"
                 :: "r"(dst), "l"(src) : "memory");
}
__device__ __forceinline__ void ldsm4(uint32_t& r0, uint32_t& r1,
                                      uint32_t& r2, uint32_t& r3, uint32_t addr) {
    asm volatile("ldmatrix.sync.aligned.m8n8.x4.shared.b16 {%0,%1,%2,%3}, [%4];"
                 : "=r"(r0), "=r"(r1), "=r"(r2), "=r"(r3) : "r"(addr));
}

// float -> half conversion pre-pass (reads float4, writes 4 halves)
__global__ void __launch_bounds__(256)
f2h_kernel(const float* __restrict__ in, __half* __restrict__ out, int n4) {
    int i = blockIdx.x * blockDim.x + threadIdx.x;
    if (i < n4) {
        float4 v = ((const float4*)in)[i];
        __half2* o = (__half2*)(out + (size_t)i * 4);
        o[0] = __floats2half2_rn(v.x, v.y);
        o[1] = __floats2half2_rn(v.z, v.w);
    }
}

// ---------------------------------------------------------------------------
// fp16 mma.sync GEMM:  Cout = epi( A[M,K] * B[N,K]^T ), fp32 accumulate.
// Block 256x128x32, 256 threads (8 warps as 4m x 2n), warp tile 64x64.
// 4-stage cp.async pipeline; ldmatrix fragment loads; mma.m16n8k16.
// ---------------------------------------------------------------------------
constexpr int BM = 256, BN = 128, BK = 32;
constexpr int STAGES = 4;
constexpr int AS_STRIDE = 40;                      // halves per smem row (80B)
constexpr int BS_STRIDE = 40;
constexpr int AS_HALVES = BM * AS_STRIDE;          // 10240
constexpr int BS_HALVES = BN * BS_STRIDE;          // 5120
constexpr int STAGE_HALVES = AS_HALVES + BS_HALVES;   // 15360 (30720 B)
constexpr int SMEM_BYTES = STAGES * STAGE_HALVES * 2; // 122880

enum { EPI_PROJ = 0, EPI_LOGITS = 2, EPI_CTX = 3, EPI_OPROJ = 4 };

template <int EPI>
__global__ void __launch_bounds__(256, 1)
mm_kernel(const __half* __restrict__ A, const __half* __restrict__ Bw,
          const float* __restrict__ biasQ, const float* __restrict__ biasK,
          const float* __restrict__ biasV,
          __half* __restrict__ dQ, __half* __restrict__ dK, __half* __restrict__ dVt,
          float* __restrict__ CoutF, __half* __restrict__ CoutH,
          int lda, int ldb, int K)
{
    extern __shared__ __half sm[];
    const int tid = threadIdx.x;
    const int wid = tid >> 5, lane = tid & 31;
    const int m0 = blockIdx.y * BM;
    const int n0 = blockIdx.x * BN;
    const int z  = blockIdx.z;

    const __half* B = Bw;
    if (EPI == EPI_PROJ)   { B  = Bw + (size_t)z * E_ * E_; }
    if (EPI == EPI_LOGITS) { A += (size_t)z * RD;      B = Bw + (size_t)z * RD; }
    if (EPI == EPI_CTX)    { A += (size_t)z * C_ * C_; B = Bw + (size_t)z * RD * C_; }

    const uint32_t smb = smem_u32(sm);

    const int warp_m = wid >> 1;          // 0..3
    const int warp_n = wid & 1;           // 0..1
    const int mb_base = warp_m * 64;
    const int nb_base = warp_n * 64;
    const int r4 = lane >> 2, c4 = lane & 3;

    // ldmatrix per-lane byte offsets (relative to stage base)
    // A (16x16 halves per x4): lanes 0-15 rows, lanes 16-31 same rows k+8
    const uint32_t a_off =
        (uint32_t)(((mb_base + (lane & 15)) * AS_STRIDE + ((lane >> 4) * 8)) * 2);
    // B x4 covers two n8 tiles x k16: lanes 0-7 n0-7 k0 / 8-15 n0-7 k8 /
    //                                 16-23 n8-15 k0 / 24-31 n8-15 k8
    const uint32_t b_off =
        (uint32_t)(((nb_base + (lane & 7) + ((lane & 16) >> 1)) * BS_STRIDE +
                    (((lane >> 3) & 1) * 8)) * 2);

    float acc[4][8][4];
#pragma unroll
    for (int a = 0; a < 4; a++)
#pragma unroll
        for (int b = 0; b < 8; b++)
#pragma unroll
            for (int c = 0; c < 4; c++) acc[a][b][c] = 0.f;

    const int NC = K / BK;

    auto load_stage = [&](int c, int s) {
        const __half* Ab = A + (size_t)m0 * lda + c * BK;
        const __half* Bb = B + (size_t)n0 * ldb + c * BK;
        const uint32_t asb = smb + (uint32_t)(s * STAGE_HALVES) * 2u;
        const uint32_t bsb = asb + AS_HALVES * 2u;
#pragma unroll
        for (int i = 0; i < 4; i++) {          // A: 256 rows x 32 halves = 1024 cp
            int q = i * 256 + tid;
            int row = q >> 2, kq = q & 3;
            cpa16(asb + (uint32_t)(row * AS_STRIDE + kq * 8) * 2u,
                  Ab + (size_t)row * lda + kq * 8);
        }
#pragma unroll
        for (int i = 0; i < 2; i++) {          // B: 128 rows x 32 halves = 512 cp
            int q = i * 256 + tid;
            int row = q >> 2, kq = q & 3;
            cpa16(bsb + (uint32_t)(row * BS_STRIDE + kq * 8) * 2u,
                  Bb + (size_t)row * ldb + kq * 8);
        }
        asm volatile("cp.async.commit_group;" ::: "memory");
    };

#pragma unroll
    for (int s = 0; s < STAGES - 1; s++)
        if (s < NC) load_stage(s, s);

    int sidx = 0;
    for (int c = 0; c < NC; c++) {
        asm volatile("cp.async.wait_group %0;" :: "n"(STAGES - 2) : "memory");
        __syncthreads();

        const int cn = c + STAGES - 1;
        if (cn < NC) {
            int sn = sidx + STAGES - 1; if (sn >= STAGES) sn -= STAGES;
            load_stage(cn, sn);
        }

        const uint32_t abase = smb + (uint32_t)(sidx * STAGE_HALVES) * 2u + a_off;
        const uint32_t bbase = smb + (uint32_t)(sidx * STAGE_HALVES + AS_HALVES) * 2u + b_off;

#pragma unroll
        for (int ks = 0; ks < BK; ks += 16) {
            uint32_t afr[4][4], bfr[8][2];
#pragma unroll
            for (int mb = 0; mb < 4; mb++)
                ldsm4(afr[mb][0], afr[mb][1], afr[mb][2], afr[mb][3],
                      abase + (uint32_t)((mb * 16 * AS_STRIDE + ks) * 2));
#pragma unroll
            for (int p = 0; p < 4; p++)
                ldsm4(bfr[2*p][0], bfr[2*p][1], bfr[2*p+1][0], bfr[2*p+1][1],
                      bbase + (uint32_t)((p * 16 * BS_STRIDE + ks) * 2));
#pragma unroll
            for (int mb = 0; mb < 4; mb++)
#pragma unroll
                for (int nb = 0; nb < 8; nb++) {
                    asm volatile(
                        "mma.sync.aligned.m16n8k16.row.col.f32.f16.f16.f32 "
                        "{%0,%1,%2,%3}, {%4,%5,%6,%7}, {%8,%9}, {%0,%1,%2,%3};"
                        : "+f"(acc[mb][nb][0]), "+f"(acc[mb][nb][1]),
                          "+f"(acc[mb][nb][2]), "+f"(acc[mb][nb][3])
                        : "r"(afr[mb][0]), "r"(afr[mb][1]),
                          "r"(afr[mb][2]), "r"(afr[mb][3]),
                          "r"(bfr[nb][0]), "r"(bfr[nb][1]));
                }
        }
        if (++sidx == STAGES) sidx = 0;
    }

    // ---- epilogue
#pragma unroll
    for (int mb = 0; mb < 4; mb++) {
#pragma unroll
        for (int half_ = 0; half_ < 2; half_++) {
            const int m = m0 + mb_base + mb * 16 + r4 + half_ * 8;
#pragma unroll
            for (int nb = 0; nb < 8; nb++) {
                const int n = n0 + nb_base + nb * 8 + c4 * 2;
                float v0 = acc[mb][nb][half_ * 2 + 0];
                float v1 = acc[mb][nb][half_ * 2 + 1];

                if (EPI == EPI_PROJ) {
                    const int r = m >> 9, ic = m & 511;
                    const int h = n >> 6, d = n & 63;
                    if (z == 0) {
                        v0 = (v0 + biasQ[n])     * SCALING;
                        v1 = (v1 + biasQ[n + 1]) * SCALING;
                        *(__half2*)(dQ + (((size_t)ic * H_ + h) * R_ + r) * D_ + d) =
                            __floats2half2_rn(v0, v1);
                    } else if (z == 1) {
                        v0 += biasK[n]; v1 += biasK[n + 1];
                        *(__half2*)(dK + (((size_t)ic * H_ + h) * R_ + r) * D_ + d) =
                            __floats2half2_rn(v0, v1);
                    } else {
                        v0 += biasV[n]; v1 += biasV[n + 1];
                        __half* dst = dVt + ((size_t)h * RD + r * D_ + d) * C_ + ic;
                        dst[0]  = __float2half_rn(v0);
                        dst[C_] = __float2half_rn(v1);
                    }
                } else if (EPI == EPI_LOGITS) {
                    float2* dst = (float2*)(CoutF + ((size_t)z * C_ + m) * C_ + n);
                    *dst = make_float2(v0, v1);
                } else if (EPI == EPI_CTX) {
                    const int r = n >> 6, d = n & 63;
                    *(__half2*)(CoutH + ((size_t)(r * C_) + m) * E_ + z * D_ + d) =
                        __floats2half2_rn(v0, v1);
                } else { // EPI_OPROJ
                    float2* dst = (float2*)(CoutF + (size_t)m * E_ + n);
                    *dst = make_float2(v0 + biasQ[n], v1 + biasQ[n + 1]);
                }
            }
        }
    }
}

// ---------------------------------------------------------------------------
// Masked softmax over rows of [H*C, C]; fp32 to d_out, fp16 to P.
// ---------------------------------------------------------------------------
__global__ void __launch_bounds__(512)
softmax_kernel(const float* __restrict__ S, __half* __restrict__ P,
               float* __restrict__ Pout)
{
    const int row = blockIdx.x;
    const int i   = row & (C_ - 1);
    const int j   = threadIdx.x;
    const int lane = j & 31, warp = j >> 5;
    __shared__ float red[16];

    float x = S[(size_t)row * C_ + j];
    if (j == i) x = -1e9f;

    float m = x;
#pragma unroll
    for (int o = 16; o > 0; o >>= 1) m = fmaxf(m, __shfl_xor_sync(~0u, m, o));
    if (lane == 0) red[warp] = m;
    __syncthreads();
    if (j < 16) {
        float t = red[j];
#pragma unroll
        for (int o = 8; o > 0; o >>= 1) t = fmaxf(t, __shfl_xor_sync(0xffffu, t, o));
        if (j == 0) red[0] = t;
    }
    __syncthreads();
    const float mx = red[0];
    __syncthreads();

    float e = __expf(x - mx);
    float sacc = e;
#pragma unroll
    for (int o = 16; o > 0; o >>= 1) sacc += __shfl_xor_sync(~0u, sacc, o);
    if (lane == 0) red[warp] = sacc;
    __syncthreads();
    if (j < 16) {
        float t = red[j];
#pragma unroll
        for (int o = 8; o > 0; o >>= 1) t += __shfl_xor_sync(0xffffu, t, o);
        if (j == 0) red[0] = t;
    }
    __syncthreads();
    const float inv = 1.0f / red[0];

    const float p = e * inv;
    const size_t idx = (size_t)row * C_ + j;
    P[idx]    = __float2half_rn(p);
    Pout[idx] = p;
}

__global__ void copy_l_kernel(const float* __restrict__ l, float* __restrict__ out)
{
    if (threadIdx.x < H_) out[threadIdx.x] = l[threadIdx.x];
}

// ---------------------------------------------------------------------------
// Launch
// ---------------------------------------------------------------------------
extern "C" void kernel_launch(void* const* d_in, const int* in_sizes, int n_in,
                              void* d_out, int out_size)
{
    const float* x  = (const float*)d_in[0];
    const float* Wq = (const float*)d_in[2];
    const float* bq = (const float*)d_in[3];
    const float* Wk = (const float*)d_in[4];
    const float* bk = (const float*)d_in[5];
    const float* Wv = (const float*)d_in[6];
    const float* bv = (const float*)d_in[7];
    const float* Wo = (const float*)d_in[8];
    const float* bo = (const float*)d_in[9];
    const float* l  = (const float*)d_in[10];
    float* out = (float*)d_out;

    __half *pXh, *pWh, *pQ, *pK, *pVt, *pP, *pCtx;
    float *pS;
    cudaGetSymbolAddress((void**)&pXh,  g_xh);
    cudaGetSymbolAddress((void**)&pWh,  g_Wh);
    cudaGetSymbolAddress((void**)&pQ,   g_Q);
    cudaGetSymbolAddress((void**)&pK,   g_K);
    cudaGetSymbolAddress((void**)&pVt,  g_Vt);
    cudaGetSymbolAddress((void**)&pS,   g_S);
    cudaGetSymbolAddress((void**)&pP,   g_P);
    cudaGetSymbolAddress((void**)&pCtx, g_ctx);

    cudaFuncSetAttribute(mm_kernel<EPI_PROJ>,   cudaFuncAttributeMaxDynamicSharedMemorySize, SMEM_BYTES);
    cudaFuncSetAttribute(mm_kernel<EPI_LOGITS>, cudaFuncAttributeMaxDynamicSharedMemorySize, SMEM_BYTES);
    cudaFuncSetAttribute(mm_kernel<EPI_CTX>,    cudaFuncAttributeMaxDynamicSharedMemorySize, SMEM_BYTES);
    cudaFuncSetAttribute(mm_kernel<EPI_OPROJ>,  cudaFuncAttributeMaxDynamicSharedMemorySize, SMEM_BYTES);

    const size_t WSZ = (size_t)E_ * E_;

    // 0) fp16 conversion of raw inputs
    {
        int n4x = (int)((size_t)M_TOK * E_ / 4);
        f2h_kernel<<<(n4x + 255) / 256, 256>>>(x, pXh, n4x);
        int n4w = (int)(WSZ / 4);
        f2h_kernel<<<(n4w + 255) / 256, 256>>>(Wq, pWh + 0 * WSZ, n4w);
        f2h_kernel<<<(n4w + 255) / 256, 256>>>(Wk, pWh + 1 * WSZ, n4w);
        f2h_kernel<<<(n4w + 255) / 256, 256>>>(Wv, pWh + 2 * WSZ, n4w);
        f2h_kernel<<<(n4w + 255) / 256, 256>>>(Wo, pWh + 3 * WSZ, n4w);
    }

    const dim3 gProj (E_ / BN, M_TOK / BM, 3);  // 6 x 128 x 3 = 2304
    const dim3 gLog  (C_ / BN, C_ / BM, H_);    // 4 x 2 x 12
    const dim3 gCtx  (RD / BN, C_ / BM, H_);    // 32 x 2 x 12
    const dim3 gOut  (E_ / BN, M_TOK / BM, 1);  // 6 x 128

    // 1) fused Q/K/V projections (z picks weight/bias/epilogue)
    mm_kernel<EPI_PROJ><<<gProj, 256, SMEM_BYTES>>>(
        pXh, pWh, bq, bk, bv, pQ, pK, pVt, nullptr, nullptr, E_, E_, E_);

    // 2) tied-row logits: S_h = Q_h * K_h^T  (K = 4096)
    mm_kernel<EPI_LOGITS><<<gLog, 256, SMEM_BYTES>>>(
        pQ, pK, nullptr, nullptr, nullptr, nullptr, nullptr, nullptr,
        pS, nullptr, HRD, HRD, RD);

    // 3) masked softmax
    softmax_kernel<<<H_ * C_, 512>>>(pS, pP, out + OUT_OFF_P);

    // 4) context: Ctx_h = P_h * Vt_h^T  (K = 512)
    mm_kernel<EPI_CTX><<<gCtx, 256, SMEM_BYTES>>>(
        pP, pVt, nullptr, nullptr, nullptr, nullptr, nullptr, nullptr,
        nullptr, pCtx, C_, C_, C_);

    // 5) output projection (bias via biasQ slot)
    mm_kernel<EPI_OPROJ><<<gOut, 256, SMEM_BYTES>>>(
        pCtx, pWh + 3 * WSZ, bo, nullptr, nullptr, nullptr, nullptr, nullptr,
        out, nullptr, E_, E_, E_);

    // 6) l passthrough
    copy_l_kernel<<<1, 32>>>(l, out + OUT_OFF_L);
}

// round 6
// speedup vs baseline: 6.1148x; 1.0284x over previous
#include <cuda_runtime.h>
#include <cuda_fp16.h>
#include <cstdint>

// ---------------------------------------------------------------------------
// Problem constants
// ---------------------------------------------------------------------------
constexpr int R_ = 64, C_ = 512, H_ = 12, D_ = 64, E_ = 768;
constexpr int M_TOK = R_ * C_;   // 32768
constexpr int RD    = R_ * D_;   // 4096
constexpr int HRD   = H_ * RD;   // 49152
constexpr long OUT_OFF_P = (long)M_TOK * E_;
constexpr long OUT_OFF_L = OUT_OFF_P + (long)H_ * C_ * C_;
constexpr float SCALING = 0.015625f;  // D^-0.5 / sqrt(R)
constexpr int KSPLIT = 4;             // logits split-K factor
constexpr int KPART  = RD / KSPLIT;   // 1024

// ---------------------------------------------------------------------------
// Scratch
// ---------------------------------------------------------------------------
__device__ __half g_xh [(size_t)M_TOK * E_];
__device__ __half g_Wh [4 * (size_t)E_ * E_];
__device__ __half g_Q  [(size_t)C_ * HRD];          // [i][h][r][d]
__device__ __half g_K  [(size_t)C_ * HRD];          // [i][h][r][d]
__device__ __half g_Vt [(size_t)H_ * RD * C_];      // [h][r*D+d][i]
__device__ float  g_Sp [(size_t)H_ * KSPLIT * C_ * C_];  // logits partials
__device__ __half g_P  [(size_t)H_ * C_ * C_];
__device__ __half g_ctx[(size_t)M_TOK * E_];

// ---------------------------------------------------------------------------
// Helpers
// ---------------------------------------------------------------------------
__device__ __forceinline__ uint32_t smem_u32(const void* p) {
    uint32_t a;
    asm("{ .reg .u64 t; cvta.to.shared.u64 t, %1; cvt.u32.u64 %0, t; }"
        : "=r"(a) : "l"(p));
    return a;
}
__device__ __forceinline__ void cpa16(uint32_t dst, const void* src) {
    asm volatile("cp.async.cg.shared.global [%0], [%1], 16;"
                 :: "r"(dst), "l"(src) : "memory");
}
__device__ __forceinline__ void ldsm4(uint32_t& r0, uint32_t& r1,
                                      uint32_t& r2, uint32_t& r3, uint32_t addr) {
    asm volatile("ldmatrix.sync.aligned.m8n8.x4.shared.b16 {%0,%1,%2,%3}, [%4];"
                 : "=r"(r0), "=r"(r1), "=r"(r2), "=r"(r3) : "r"(addr));
}

// float -> half conversion: x (single tensor)
__global__ void __launch_bounds__(256)
f2h_kernel(const float* __restrict__ in, __half* __restrict__ out, int n4) {
    int i = blockIdx.x * blockDim.x + threadIdx.x;
    if (i < n4) {
        float4 v = ((const float4*)in)[i];
        __half2* o = (__half2*)(out + (size_t)i * 4);
        o[0] = __floats2half2_rn(v.x, v.y);
        o[1] = __floats2half2_rn(v.z, v.w);
    }
}

// float -> half for the 4 weight matrices in one launch (grid.y selects W)
__global__ void __launch_bounds__(256)
f2h_w_kernel(const float* __restrict__ w0, const float* __restrict__ w1,
             const float* __restrict__ w2, const float* __restrict__ w3,
             __half* __restrict__ out, int n4) {
    int i = blockIdx.x * blockDim.x + threadIdx.x;
    if (i >= n4) return;
    const float* src = (blockIdx.y == 0) ? w0 : (blockIdx.y == 1) ? w1
                      : (blockIdx.y == 2) ? w2 : w3;
    float4 v = ((const float4*)src)[i];
    __half2* o = (__half2*)(out + (size_t)blockIdx.y * E_ * E_ + (size_t)i * 4);
    o[0] = __floats2half2_rn(v.x, v.y);
    o[1] = __floats2half2_rn(v.z, v.w);
}

// ---------------------------------------------------------------------------
// fp16 mma.sync GEMM, fp32 accumulate. Block 256x128x32, 8 warps (4m x 2n).
// 4-stage cp.async pipeline; ldmatrix fragment loads; mma.m16n8k16.
// ---------------------------------------------------------------------------
constexpr int BM = 256, BN = 128, BK = 32;
constexpr int STAGES = 4;
constexpr int AS_STRIDE = 40;
constexpr int BS_STRIDE = 40;
constexpr int AS_HALVES = BM * AS_STRIDE;
constexpr int BS_HALVES = BN * BS_STRIDE;
constexpr int STAGE_HALVES = AS_HALVES + BS_HALVES;
constexpr int SMEM_BYTES = STAGES * STAGE_HALVES * 2;   // 122880

enum { EPI_PROJ = 0, EPI_LOGITS = 2, EPI_CTX = 3, EPI_OPROJ = 4 };

template <int EPI>
__global__ void __launch_bounds__(256, 1)
mm_kernel(const __half* __restrict__ A, const __half* __restrict__ Bw,
          const float* __restrict__ biasQ, const float* __restrict__ biasK,
          const float* __restrict__ biasV,
          __half* __restrict__ dQ, __half* __restrict__ dK, __half* __restrict__ dVt,
          float* __restrict__ CoutF, __half* __restrict__ CoutH,
          int lda, int ldb, int K)
{
    extern __shared__ __half sm[];
    const int tid = threadIdx.x;
    const int wid = tid >> 5, lane = tid & 31;
    const int m0 = blockIdx.y * BM;
    const int n0 = blockIdx.x * BN;
    const int z  = blockIdx.z;

    const __half* B = Bw;
    if (EPI == EPI_PROJ)   { B  = Bw + (size_t)z * E_ * E_; }
    if (EPI == EPI_LOGITS) {
        const int head = z >> 2, kh = z & 3;     // z = head*4 + ksplit
        A += (size_t)head * RD + (size_t)kh * KPART;
        B  = Bw + (size_t)head * RD + (size_t)kh * KPART;
    }
    if (EPI == EPI_CTX)    { A += (size_t)z * C_ * C_; B = Bw + (size_t)z * RD * C_; }

    const uint32_t smb = smem_u32(sm);

    const int warp_m = wid >> 1;
    const int warp_n = wid & 1;
    const int mb_base = warp_m * 64;
    const int nb_base = warp_n * 64;
    const int r4 = lane >> 2, c4 = lane & 3;

    const uint32_t a_off =
        (uint32_t)(((mb_base + (lane & 15)) * AS_STRIDE + ((lane >> 4) * 8)) * 2);
    const uint32_t b_off =
        (uint32_t)(((nb_base + (lane & 7) + ((lane & 16) >> 1)) * BS_STRIDE +
                    (((lane >> 3) & 1) * 8)) * 2);

    float acc[4][8][4];
#pragma unroll
    for (int a = 0; a < 4; a++)
#pragma unroll
        for (int b = 0; b < 8; b++)
#pragma unroll
            for (int c = 0; c < 4; c++) acc[a][b][c] = 0.f;

    const int NC = K / BK;

    auto load_stage = [&](int c, int s) {
        const __half* Ab = A + (size_t)m0 * lda + c * BK;
        const __half* Bb = B + (size_t)n0 * ldb + c * BK;
        const uint32_t asb = smb + (uint32_t)(s * STAGE_HALVES) * 2u;
        const uint32_t bsb = asb + AS_HALVES * 2u;
#pragma unroll
        for (int i = 0; i < 4; i++) {
            int q = i * 256 + tid;
            int row = q >> 2, kq = q & 3;
            cpa16(asb + (uint32_t)(row * AS_STRIDE + kq * 8) * 2u,
                  Ab + (size_t)row * lda + kq * 8);
        }
#pragma unroll
        for (int i = 0; i < 2; i++) {
            int q = i * 256 + tid;
            int row = q >> 2, kq = q & 3;
            cpa16(bsb + (uint32_t)(row * BS_STRIDE + kq * 8) * 2u,
                  Bb + (size_t)row * ldb + kq * 8);
        }
        asm volatile("cp.async.commit_group;" ::: "memory");
    };

#pragma unroll
    for (int s = 0; s < STAGES - 1; s++)
        if (s < NC) load_stage(s, s);

    int sidx = 0;
    for (int c = 0; c < NC; c++) {
        asm volatile("cp.async.wait_group %0;" :: "n"(STAGES - 2) : "memory");
        __syncthreads();

        const int cn = c + STAGES - 1;
        if (cn < NC) {
            int sn = sidx + STAGES - 1; if (sn >= STAGES) sn -= STAGES;
            load_stage(cn, sn);
        }

        const uint32_t abase = smb + (uint32_t)(sidx * STAGE_HALVES) * 2u + a_off;
        const uint32_t bbase = smb + (uint32_t)(sidx * STAGE_HALVES + AS_HALVES) * 2u + b_off;

#pragma unroll
        for (int ks = 0; ks < BK; ks += 16) {
            uint32_t afr[4][4], bfr[8][2];
#pragma unroll
            for (int mb = 0; mb < 4; mb++)
                ldsm4(afr[mb][0], afr[mb][1], afr[mb][2], afr[mb][3],
                      abase + (uint32_t)((mb * 16 * AS_STRIDE + ks) * 2));
#pragma unroll
            for (int p = 0; p < 4; p++)
                ldsm4(bfr[2*p][0], bfr[2*p][1], bfr[2*p+1][0], bfr[2*p+1][1],
                      bbase + (uint32_t)((p * 16 * BS_STRIDE + ks) * 2));
#pragma unroll
            for (int mb = 0; mb < 4; mb++)
#pragma unroll
                for (int nb = 0; nb < 8; nb++) {
                    asm volatile(
                        "mma.sync.aligned.m16n8k16.row.col.f32.f16.f16.f32 "
                        "{%0,%1,%2,%3}, {%4,%5,%6,%7}, {%8,%9}, {%0,%1,%2,%3};"
                        : "+f"(acc[mb][nb][0]), "+f"(acc[mb][nb][1]),
                          "+f"(acc[mb][nb][2]), "+f"(acc[mb][nb][3])
                        : "r"(afr[mb][0]), "r"(afr[mb][1]),
                          "r"(afr[mb][2]), "r"(afr[mb][3]),
                          "r"(bfr[nb][0]), "r"(bfr[nb][1]));
                }
        }
        if (++sidx == STAGES) sidx = 0;
    }

    // ---- epilogue
#pragma unroll
    for (int mb = 0; mb < 4; mb++) {
#pragma unroll
        for (int half_ = 0; half_ < 2; half_++) {
            const int m = m0 + mb_base + mb * 16 + r4 + half_ * 8;
#pragma unroll
            for (int nb = 0; nb < 8; nb++) {
                const int n = n0 + nb_base + nb * 8 + c4 * 2;
                float v0 = acc[mb][nb][half_ * 2 + 0];
                float v1 = acc[mb][nb][half_ * 2 + 1];

                if (EPI == EPI_PROJ) {
                    const int r = m >> 9, ic = m & 511;
                    const int h = n >> 6, d = n & 63;
                    if (z == 0) {
                        v0 = (v0 + biasQ[n])     * SCALING;
                        v1 = (v1 + biasQ[n + 1]) * SCALING;
                        *(__half2*)(dQ + (((size_t)ic * H_ + h) * R_ + r) * D_ + d) =
                            __floats2half2_rn(v0, v1);
                    } else if (z == 1) {
                        v0 += biasK[n]; v1 += biasK[n + 1];
                        *(__half2*)(dK + (((size_t)ic * H_ + h) * R_ + r) * D_ + d) =
                            __floats2half2_rn(v0, v1);
                    } else {
                        v0 += biasV[n]; v1 += biasV[n + 1];
                        __half* dst = dVt + ((size_t)h * RD + r * D_ + d) * C_ + ic;
                        dst[0]  = __float2half_rn(v0);
                        dst[C_] = __float2half_rn(v1);
                    }
                } else if (EPI == EPI_LOGITS) {
                    // z-th partial buffer, laid out [H*KSPLIT][C][C]
                    float2* dst = (float2*)(CoutF + ((size_t)z * C_ + m) * C_ + n);
                    *dst = make_float2(v0, v1);
                } else if (EPI == EPI_CTX) {
                    const int r = n >> 6, d = n & 63;
                    *(__half2*)(CoutH + ((size_t)(r * C_) + m) * E_ + z * D_ + d) =
                        __floats2half2_rn(v0, v1);
                } else { // EPI_OPROJ
                    float2* dst = (float2*)(CoutF + (size_t)m * E_ + n);
                    *dst = make_float2(v0 + biasQ[n], v1 + biasQ[n + 1]);
                }
            }
        }
    }
}

// ---------------------------------------------------------------------------
// Masked softmax; sums KSPLIT logits partials. fp32 to d_out, fp16 to P.
// ---------------------------------------------------------------------------
__global__ void __launch_bounds__(512)
softmax_kernel(const float* __restrict__ Sp, __half* __restrict__ P,
               float* __restrict__ Pout)
{
    const int row = blockIdx.x;          // h*C + i
    const int h   = row >> 9;            // row / C_
    const int i   = row & (C_ - 1);
    const int j   = threadIdx.x;
    const int lane = j & 31, warp = j >> 5;
    __shared__ float red[16];

    const float* base = Sp + (((size_t)h * KSPLIT) * C_ + i) * C_ + j;
    float x = base[0];
#pragma unroll
    for (int kh = 1; kh < KSPLIT; kh++)
        x += base[(size_t)kh * C_ * C_];
    if (j == i) x = -1e9f;

    float m = x;
#pragma unroll
    for (int o = 16; o > 0; o >>= 1) m = fmaxf(m, __shfl_xor_sync(~0u, m, o));
    if (lane == 0) red[warp] = m;
    __syncthreads();
    if (j < 16) {
        float t = red[j];
#pragma unroll
        for (int o = 8; o > 0; o >>= 1) t = fmaxf(t, __shfl_xor_sync(0xffffu, t, o));
        if (j == 0) red[0] = t;
    }
    __syncthreads();
    const float mx = red[0];
    __syncthreads();

    float e = __expf(x - mx);
    float sacc = e;
#pragma unroll
    for (int o = 16; o > 0; o >>= 1) sacc += __shfl_xor_sync(~0u, sacc, o);
    if (lane == 0) red[warp] = sacc;
    __syncthreads();
    if (j < 16) {
        float t = red[j];
#pragma unroll
        for (int o = 8; o > 0; o >>= 1) t += __shfl_xor_sync(0xffffu, t, o);
        if (j == 0) red[0] = t;
    }
    __syncthreads();
    const float inv = 1.0f / red[0];

    const float p = e * inv;
    const size_t idx = (size_t)row * C_ + j;
    P[idx]    = __float2half_rn(p);
    Pout[idx] = p;
}

__global__ void copy_l_kernel(const float* __restrict__ l, float* __restrict__ out)
{
    if (threadIdx.x < H_) out[threadIdx.x] = l[threadIdx.x];
}

// ---------------------------------------------------------------------------
// Launch
// ---------------------------------------------------------------------------
extern "C" void kernel_launch(void* const* d_in, const int* in_sizes, int n_in,
                              void* d_out, int out_size)
{
    const float* x  = (const float*)d_in[0];
    const float* Wq = (const float*)d_in[2];
    const float* bq = (const float*)d_in[3];
    const float* Wk = (const float*)d_in[4];
    const float* bk = (const float*)d_in[5];
    const float* Wv = (const float*)d_in[6];
    const float* bv = (const float*)d_in[7];
    const float* Wo = (const float*)d_in[8];
    const float* bo = (const float*)d_in[9];
    const float* l  = (const float*)d_in[10];
    float* out = (float*)d_out;

    __half *pXh, *pWh, *pQ, *pK, *pVt, *pP, *pCtx;
    float *pSp;
    cudaGetSymbolAddress((void**)&pXh,  g_xh);
    cudaGetSymbolAddress((void**)&pWh,  g_Wh);
    cudaGetSymbolAddress((void**)&pQ,   g_Q);
    cudaGetSymbolAddress((void**)&pK,   g_K);
    cudaGetSymbolAddress((void**)&pVt,  g_Vt);
    cudaGetSymbolAddress((void**)&pSp,  g_Sp);
    cudaGetSymbolAddress((void**)&pP,   g_P);
    cudaGetSymbolAddress((void**)&pCtx, g_ctx);

    cudaFuncSetAttribute(mm_kernel<EPI_PROJ>,   cudaFuncAttributeMaxDynamicSharedMemorySize, SMEM_BYTES);
    cudaFuncSetAttribute(mm_kernel<EPI_LOGITS>, cudaFuncAttributeMaxDynamicSharedMemorySize, SMEM_BYTES);
    cudaFuncSetAttribute(mm_kernel<EPI_CTX>,    cudaFuncAttributeMaxDynamicSharedMemorySize, SMEM_BYTES);
    cudaFuncSetAttribute(mm_kernel<EPI_OPROJ>,  cudaFuncAttributeMaxDynamicSharedMemorySize, SMEM_BYTES);

    const size_t WSZ = (size_t)E_ * E_;

    // 0) fp16 conversion: x in one launch, all 4 W's in one launch
    {
        int n4x = (int)((size_t)M_TOK * E_ / 4);
        f2h_kernel<<<(n4x + 255) / 256, 256>>>(x, pXh, n4x);
        int n4w = (int)(WSZ / 4);
        dim3 gW((n4w + 255) / 256, 4);
        f2h_w_kernel<<<gW, 256>>>(Wq, Wk, Wv, Wo, pWh, n4w);
    }

    const dim3 gProj (E_ / BN, M_TOK / BM, 3);          // 2304 CTAs
    const dim3 gLog  (C_ / BN, C_ / BM, H_ * KSPLIT);   // 4 x 2 x 48 = 384
    const dim3 gCtx  (RD / BN, C_ / BM, H_);            // 768
    const dim3 gOut  (E_ / BN, M_TOK / BM, 1);          // 768

    // 1) fused Q/K/V projections
    mm_kernel<EPI_PROJ><<<gProj, 256, SMEM_BYTES>>>(
        pXh, pWh, bq, bk, bv, pQ, pK, pVt, nullptr, nullptr, E_, E_, E_);

    // 2) tied-row logits, split-K x4 (z = head*4 + kpart, K = 1024 each)
    mm_kernel<EPI_LOGITS><<<gLog, 256, SMEM_BYTES>>>(
        pQ, pK, nullptr, nullptr, nullptr, nullptr, nullptr, nullptr,
        pSp, nullptr, HRD, HRD, KPART);

    // 3) masked softmax (sums the 4 partials)
    softmax_kernel<<<H_ * C_, 512>>>(pSp, pP, out + OUT_OFF_P);

    // 4) context: Ctx_h = P_h * Vt_h^T  (K = 512)
    mm_kernel<EPI_CTX><<<gCtx, 256, SMEM_BYTES>>>(
        pP, pVt, nullptr, nullptr, nullptr, nullptr, nullptr, nullptr,
        nullptr, pCtx, C_, C_, C_);

    // 5) output projection
    mm_kernel<EPI_OPROJ><<<gOut, 256, SMEM_BYTES>>>(
        pCtx, pWh + 3 * WSZ, bo, nullptr, nullptr, nullptr, nullptr, nullptr,
        out, nullptr, E_, E_, E_);

    // 6) l passthrough
    copy_l_kernel<<<1, 32>>>(l, out + OUT_OFF_L);
}

// round 7
// speedup vs baseline: 7.2145x; 1.1798x over previous
#include <cuda_runtime.h>
#include <cuda_fp16.h>
#include <cstdint>

// ---------------------------------------------------------------------------
// Problem constants
// ---------------------------------------------------------------------------
constexpr int R_ = 64, C_ = 512, H_ = 12, D_ = 64, E_ = 768;
constexpr int M_TOK = R_ * C_;   // 32768
constexpr int RD    = R_ * D_;   // 4096
constexpr int HRD   = H_ * RD;   // 49152
constexpr long OUT_OFF_P = (long)M_TOK * E_;
constexpr long OUT_OFF_L = OUT_OFF_P + (long)H_ * C_ * C_;
constexpr float SCALING = 0.015625f;  // D^-0.5 / sqrt(R)
constexpr int KSPLIT = 4;
constexpr int KPART  = RD / KSPLIT;   // 1024

// ---------------------------------------------------------------------------
// Scratch
// ---------------------------------------------------------------------------
__device__ __half g_xh [(size_t)M_TOK * E_];
__device__ __half g_Wh [4 * (size_t)E_ * E_];
__device__ __half g_Q  [(size_t)C_ * HRD];          // [i][h][r][d]
__device__ __half g_K  [(size_t)C_ * HRD];          // [i][h][r][d]
__device__ __half g_Vt [(size_t)H_ * RD * C_];      // [h][r*D+d][i]
__device__ float  g_Sp [(size_t)H_ * KSPLIT * C_ * C_];
__device__ __half g_P  [(size_t)H_ * C_ * C_];
__device__ __half g_ctx[(size_t)M_TOK * E_];

// ---------------------------------------------------------------------------
// Helpers
// ---------------------------------------------------------------------------
__device__ __forceinline__ uint32_t smem_u32(const void* p) {
    uint32_t a;
    asm("{ .reg .u64 t; cvta.to.shared.u64 t, %1; cvt.u32.u64 %0, t; }"
        : "=r"(a) : "l"(p));
    return a;
}
__device__ __forceinline__ void cpa16(uint32_t dst, const void* src) {
    asm volatile("cp.async.cg.shared.global [%0], [%1], 16;"
                 :: "r"(dst), "l"(src) : "memory");
}
__device__ __forceinline__ void ldsm4(uint32_t& r0, uint32_t& r1,
                                      uint32_t& r2, uint32_t& r3, uint32_t addr) {
    asm volatile("ldmatrix.sync.aligned.m8n8.x4.shared.b16 {%0,%1,%2,%3}, [%4];"
                 : "=r"(r0), "=r"(r1), "=r"(r2), "=r"(r3) : "r"(addr));
}

__global__ void __launch_bounds__(256)
f2h_kernel(const float* __restrict__ in, __half* __restrict__ out, int n4) {
    int i = blockIdx.x * blockDim.x + threadIdx.x;
    if (i < n4) {
        float4 v = ((const float4*)in)[i];
        __half2* o = (__half2*)(out + (size_t)i * 4);
        o[0] = __floats2half2_rn(v.x, v.y);
        o[1] = __floats2half2_rn(v.z, v.w);
    }
}

__global__ void __launch_bounds__(256)
f2h_w_kernel(const float* __restrict__ w0, const float* __restrict__ w1,
             const float* __restrict__ w2, const float* __restrict__ w3,
             __half* __restrict__ out, int n4) {
    int i = blockIdx.x * blockDim.x + threadIdx.x;
    if (i >= n4) return;
    const float* src = (blockIdx.y == 0) ? w0 : (blockIdx.y == 1) ? w1
                      : (blockIdx.y == 2) ? w2 : w3;
    float4 v = ((const float4*)src)[i];
    __half2* o = (__half2*)(out + (size_t)blockIdx.y * E_ * E_ + (size_t)i * 4);
    o[0] = __floats2half2_rn(v.x, v.y);
    o[1] = __floats2half2_rn(v.z, v.w);
}

// ---------------------------------------------------------------------------
// fp16 mma.sync GEMM, fp32 accumulate. Block 128x128x32, 8 warps (4m x 2n),
// warp tile 32x64. 4-stage cp.async pipeline; 2 CTAs/SM.
// ---------------------------------------------------------------------------
constexpr int BM = 128, BN = 128, BK = 32;
constexpr int STAGES = 4;
constexpr int AS_STRIDE = 40;                     // halves per row (80 B)
constexpr int BS_STRIDE = 40;
constexpr int AS_HALVES = BM * AS_STRIDE;         // 5120
constexpr int BS_HALVES = BN * BS_STRIDE;         // 5120
constexpr int STAGE_HALVES = AS_HALVES + BS_HALVES;   // 10240 (20480 B)
constexpr int SMEM_BYTES = STAGES * STAGE_HALVES * 2; // 81920

enum { EPI_PROJ = 0, EPI_LOGITS = 2, EPI_CTX = 3, EPI_OPROJ = 4 };

template <int EPI>
__global__ void __launch_bounds__(256, 2)
mm_kernel(const __half* __restrict__ A, const __half* __restrict__ Bw,
          const float* __restrict__ biasQ, const float* __restrict__ biasK,
          const float* __restrict__ biasV,
          __half* __restrict__ dQ, __half* __restrict__ dK, __half* __restrict__ dVt,
          float* __restrict__ CoutF, __half* __restrict__ CoutH,
          int lda, int ldb, int K)
{
    extern __shared__ __half sm[];
    const int tid = threadIdx.x;
    const int wid = tid >> 5, lane = tid & 31;
    const int m0 = blockIdx.y * BM;
    const int n0 = blockIdx.x * BN;
    const int z  = blockIdx.z;

    const __half* B = Bw;
    if (EPI == EPI_PROJ)   { B  = Bw + (size_t)z * E_ * E_; }
    if (EPI == EPI_LOGITS) {
        const int head = z >> 2, kh = z & 3;
        A += (size_t)head * RD + (size_t)kh * KPART;
        B  = Bw + (size_t)head * RD + (size_t)kh * KPART;
    }
    if (EPI == EPI_CTX)    { A += (size_t)z * C_ * C_; B = Bw + (size_t)z * RD * C_; }

    const uint32_t smb = smem_u32(sm);

    const int warp_m = wid >> 1;          // 0..3 -> 32-row slices
    const int warp_n = wid & 1;           // 0..1 -> 64-col slices
    const int mb_base = warp_m * 32;
    const int nb_base = warp_n * 64;
    const int r4 = lane >> 2, c4 = lane & 3;

    const uint32_t a_off =
        (uint32_t)(((mb_base + (lane & 15)) * AS_STRIDE + ((lane >> 4) * 8)) * 2);
    const uint32_t b_off =
        (uint32_t)(((nb_base + (lane & 7) + ((lane & 16) >> 1)) * BS_STRIDE +
                    (((lane >> 3) & 1) * 8)) * 2);

    float acc[2][8][4];
#pragma unroll
    for (int a = 0; a < 2; a++)
#pragma unroll
        for (int b = 0; b < 8; b++)
#pragma unroll
            for (int c = 0; c < 4; c++) acc[a][b][c] = 0.f;

    const int NC = K / BK;

    auto load_stage = [&](int c, int s) {
        const __half* Ab = A + (size_t)m0 * lda + c * BK;
        const __half* Bb = B + (size_t)n0 * ldb + c * BK;
        const uint32_t asb = smb + (uint32_t)(s * STAGE_HALVES) * 2u;
        const uint32_t bsb = asb + AS_HALVES * 2u;
#pragma unroll
        for (int i = 0; i < 2; i++) {          // A: 128 rows x 4 f8 = 512 cp
            int q = i * 256 + tid;
            int row = q >> 2, kq = q & 3;
            cpa16(asb + (uint32_t)(row * AS_STRIDE + kq * 8) * 2u,
                  Ab + (size_t)row * lda + kq * 8);
        }
#pragma unroll
        for (int i = 0; i < 2; i++) {          // B: 128 rows x 4 f8 = 512 cp
            int q = i * 256 + tid;
            int row = q >> 2, kq = q & 3;
            cpa16(bsb + (uint32_t)(row * BS_STRIDE + kq * 8) * 2u,
                  Bb + (size_t)row * ldb + kq * 8);
        }
        asm volatile("cp.async.commit_group;" ::: "memory");
    };

#pragma unroll
    for (int s = 0; s < STAGES - 1; s++)
        if (s < NC) load_stage(s, s);

    int sidx = 0;
    for (int c = 0; c < NC; c++) {
        asm volatile("cp.async.wait_group %0;" :: "n"(STAGES - 2) : "memory");
        __syncthreads();

        const int cn = c + STAGES - 1;
        if (cn < NC) {
            int sn = sidx + STAGES - 1; if (sn >= STAGES) sn -= STAGES;
            load_stage(cn, sn);
        }

        const uint32_t abase = smb + (uint32_t)(sidx * STAGE_HALVES) * 2u + a_off;
        const uint32_t bbase = smb + (uint32_t)(sidx * STAGE_HALVES + AS_HALVES) * 2u + b_off;

#pragma unroll
        for (int ks = 0; ks < BK; ks += 16) {
            uint32_t afr[2][4], bfr[8][2];
#pragma unroll
            for (int mb = 0; mb < 2; mb++)
                ldsm4(afr[mb][0], afr[mb][1], afr[mb][2], afr[mb][3],
                      abase + (uint32_t)((mb * 16 * AS_STRIDE + ks) * 2));
#pragma unroll
            for (int p = 0; p < 4; p++)
                ldsm4(bfr[2*p][0], bfr[2*p][1], bfr[2*p+1][0], bfr[2*p+1][1],
                      bbase + (uint32_t)((p * 16 * BS_STRIDE + ks) * 2));
#pragma unroll
            for (int mb = 0; mb < 2; mb++)
#pragma unroll
                for (int nb = 0; nb < 8; nb++) {
                    asm volatile(
                        "mma.sync.aligned.m16n8k16.row.col.f32.f16.f16.f32 "
                        "{%0,%1,%2,%3}, {%4,%5,%6,%7}, {%8,%9}, {%0,%1,%2,%3};"
                        : "+f"(acc[mb][nb][0]), "+f"(acc[mb][nb][1]),
                          "+f"(acc[mb][nb][2]), "+f"(acc[mb][nb][3])
                        : "r"(afr[mb][0]), "r"(afr[mb][1]),
                          "r"(afr[mb][2]), "r"(afr[mb][3]),
                          "r"(bfr[nb][0]), "r"(bfr[nb][1]));
                }
        }
        if (++sidx == STAGES) sidx = 0;
    }

    // ---- epilogue
#pragma unroll
    for (int mb = 0; mb < 2; mb++) {
#pragma unroll
        for (int half_ = 0; half_ < 2; half_++) {
            const int m = m0 + mb_base + mb * 16 + r4 + half_ * 8;
#pragma unroll
            for (int nb = 0; nb < 8; nb++) {
                const int n = n0 + nb_base + nb * 8 + c4 * 2;
                float v0 = acc[mb][nb][half_ * 2 + 0];
                float v1 = acc[mb][nb][half_ * 2 + 1];

                if (EPI == EPI_PROJ) {
                    const int r = m >> 9, ic = m & 511;
                    const int h = n >> 6, d = n & 63;
                    if (z == 0) {
                        v0 = (v0 + biasQ[n])     * SCALING;
                        v1 = (v1 + biasQ[n + 1]) * SCALING;
                        *(__half2*)(dQ + (((size_t)ic * H_ + h) * R_ + r) * D_ + d) =
                            __floats2half2_rn(v0, v1);
                    } else if (z == 1) {
                        v0 += biasK[n]; v1 += biasK[n + 1];
                        *(__half2*)(dK + (((size_t)ic * H_ + h) * R_ + r) * D_ + d) =
                            __floats2half2_rn(v0, v1);
                    } else {
                        v0 += biasV[n]; v1 += biasV[n + 1];
                        __half* dst = dVt + ((size_t)h * RD + r * D_ + d) * C_ + ic;
                        dst[0]  = __float2half_rn(v0);
                        dst[C_] = __float2half_rn(v1);
                    }
                } else if (EPI == EPI_LOGITS) {
                    float2* dst = (float2*)(CoutF + ((size_t)z * C_ + m) * C_ + n);
                    *dst = make_float2(v0, v1);
                } else if (EPI == EPI_CTX) {
                    const int r = n >> 6, d = n & 63;
                    *(__half2*)(CoutH + ((size_t)(r * C_) + m) * E_ + z * D_ + d) =
                        __floats2half2_rn(v0, v1);
                } else { // EPI_OPROJ
                    float2* dst = (float2*)(CoutF + (size_t)m * E_ + n);
                    *dst = make_float2(v0 + biasQ[n], v1 + biasQ[n + 1]);
                }
            }
        }
    }
}

// ---------------------------------------------------------------------------
// Masked softmax; sums KSPLIT partials. fp32 to d_out, fp16 to P.
// ---------------------------------------------------------------------------
__global__ void __launch_bounds__(512)
softmax_kernel(const float* __restrict__ Sp, __half* __restrict__ P,
               float* __restrict__ Pout)
{
    const int row = blockIdx.x;
    const int h   = row >> 9;
    const int i   = row & (C_ - 1);
    const int j   = threadIdx.x;
    const int lane = j & 31, warp = j >> 5;
    __shared__ float red[16];

    const float* base = Sp + (((size_t)h * KSPLIT) * C_ + i) * C_ + j;
    float x = base[0];
#pragma unroll
    for (int kh = 1; kh < KSPLIT; kh++)
        x += base[(size_t)kh * C_ * C_];
    if (j == i) x = -1e9f;

    float m = x;
#pragma unroll
    for (int o = 16; o > 0; o >>= 1) m = fmaxf(m, __shfl_xor_sync(~0u, m, o));
    if (lane == 0) red[warp] = m;
    __syncthreads();
    if (j < 16) {
        float t = red[j];
#pragma unroll
        for (int o = 8; o > 0; o >>= 1) t = fmaxf(t, __shfl_xor_sync(0xffffu, t, o));
        if (j == 0) red[0] = t;
    }
    __syncthreads();
    const float mx = red[0];
    __syncthreads();

    float e = __expf(x - mx);
    float sacc = e;
#pragma unroll
    for (int o = 16; o > 0; o >>= 1) sacc += __shfl_xor_sync(~0u, sacc, o);
    if (lane == 0) red[warp] = sacc;
    __syncthreads();
    if (j < 16) {
        float t = red[j];
#pragma unroll
        for (int o = 8; o > 0; o >>= 1) t += __shfl_xor_sync(0xffffu, t, o);
        if (j == 0) red[0] = t;
    }
    __syncthreads();
    const float inv = 1.0f / red[0];

    const float p = e * inv;
    const size_t idx = (size_t)row * C_ + j;
    P[idx]    = __float2half_rn(p);
    Pout[idx] = p;
}

__global__ void copy_l_kernel(const float* __restrict__ l, float* __restrict__ out)
{
    if (threadIdx.x < H_) out[threadIdx.x] = l[threadIdx.x];
}

// ---------------------------------------------------------------------------
// Launch
// ---------------------------------------------------------------------------
extern "C" void kernel_launch(void* const* d_in, const int* in_sizes, int n_in,
                              void* d_out, int out_size)
{
    const float* x  = (const float*)d_in[0];
    const float* Wq = (const float*)d_in[2];
    const float* bq = (const float*)d_in[3];
    const float* Wk = (const float*)d_in[4];
    const float* bk = (const float*)d_in[5];
    const float* Wv = (const float*)d_in[6];
    const float* bv = (const float*)d_in[7];
    const float* Wo = (const float*)d_in[8];
    const float* bo = (const float*)d_in[9];
    const float* l  = (const float*)d_in[10];
    float* out = (float*)d_out;

    __half *pXh, *pWh, *pQ, *pK, *pVt, *pP, *pCtx;
    float *pSp;
    cudaGetSymbolAddress((void**)&pXh,  g_xh);
    cudaGetSymbolAddress((void**)&pWh,  g_Wh);
    cudaGetSymbolAddress((void**)&pQ,   g_Q);
    cudaGetSymbolAddress((void**)&pK,   g_K);
    cudaGetSymbolAddress((void**)&pVt,  g_Vt);
    cudaGetSymbolAddress((void**)&pSp,  g_Sp);
    cudaGetSymbolAddress((void**)&pP,   g_P);
    cudaGetSymbolAddress((void**)&pCtx, g_ctx);

    cudaFuncSetAttribute(mm_kernel<EPI_PROJ>,   cudaFuncAttributeMaxDynamicSharedMemorySize, SMEM_BYTES);
    cudaFuncSetAttribute(mm_kernel<EPI_LOGITS>, cudaFuncAttributeMaxDynamicSharedMemorySize, SMEM_BYTES);
    cudaFuncSetAttribute(mm_kernel<EPI_CTX>,    cudaFuncAttributeMaxDynamicSharedMemorySize, SMEM_BYTES);
    cudaFuncSetAttribute(mm_kernel<EPI_OPROJ>,  cudaFuncAttributeMaxDynamicSharedMemorySize, SMEM_BYTES);

    const size_t WSZ = (size_t)E_ * E_;

    // 0) fp16 conversion
    {
        int n4x = (int)((size_t)M_TOK * E_ / 4);
        f2h_kernel<<<(n4x + 255) / 256, 256>>>(x, pXh, n4x);
        int n4w = (int)(WSZ / 4);
        dim3 gW((n4w + 255) / 256, 4);
        f2h_w_kernel<<<gW, 256>>>(Wq, Wk, Wv, Wo, pWh, n4w);
    }

    const dim3 gProj (E_ / BN, M_TOK / BM, 3);          // 6 x 256 x 3
    const dim3 gLog  (C_ / BN, C_ / BM, H_ * KSPLIT);   // 4 x 4 x 48
    const dim3 gCtx  (RD / BN, C_ / BM, H_);            // 32 x 4 x 12
    const dim3 gOut  (E_ / BN, M_TOK / BM, 1);          // 6 x 256

    // 1) fused Q/K/V projections
    mm_kernel<EPI_PROJ><<<gProj, 256, SMEM_BYTES>>>(
        pXh, pWh, bq, bk, bv, pQ, pK, pVt, nullptr, nullptr, E_, E_, E_);

    // 2) tied-row logits, split-K x4
    mm_kernel<EPI_LOGITS><<<gLog, 256, SMEM_BYTES>>>(
        pQ, pK, nullptr, nullptr, nullptr, nullptr, nullptr, nullptr,
        pSp, nullptr, HRD, HRD, KPART);

    // 3) masked softmax
    softmax_kernel<<<H_ * C_, 512>>>(pSp, pP, out + OUT_OFF_P);

    // 4) context
    mm_kernel<EPI_CTX><<<gCtx, 256, SMEM_BYTES>>>(
        pP, pVt, nullptr, nullptr, nullptr, nullptr, nullptr, nullptr,
        nullptr, pCtx, C_, C_, C_);

    // 5) output projection
    mm_kernel<EPI_OPROJ><<<gOut, 256, SMEM_BYTES>>>(
        pCtx, pWh + 3 * WSZ, bo, nullptr, nullptr, nullptr, nullptr, nullptr,
        out, nullptr, E_, E_, E_);

    // 6) l passthrough
    copy_l_kernel<<<1, 32>>>(l, out + OUT_OFF_L);
}

// round 8
// speedup vs baseline: 7.5295x; 1.0437x over previous
#include <cuda_runtime.h>
#include <cuda_fp16.h>
#include <cstdint>

// ---------------------------------------------------------------------------
// Problem constants
// ---------------------------------------------------------------------------
constexpr int R_ = 64, C_ = 512, H_ = 12, D_ = 64, E_ = 768;
constexpr int M_TOK = R_ * C_;   // 32768
constexpr int RD    = R_ * D_;   // 4096
constexpr int HRD   = H_ * RD;   // 49152
constexpr long OUT_OFF_P = (long)M_TOK * E_;
constexpr long OUT_OFF_L = OUT_OFF_P + (long)H_ * C_ * C_;
constexpr float SCALING = 0.015625f;  // D^-0.5 / sqrt(R)
constexpr int KSPLIT = 4;
constexpr int KPART  = RD / KSPLIT;   // 1024

// ---------------------------------------------------------------------------
// Scratch
// ---------------------------------------------------------------------------
__device__ __half g_xh [(size_t)M_TOK * E_];
__device__ __half g_Wh [4 * (size_t)E_ * E_];
__device__ __half g_Q  [(size_t)C_ * HRD];          // [i][h][r][d]
__device__ __half g_K  [(size_t)C_ * HRD];          // [i][h][r][d]
__device__ __half g_Vt [(size_t)H_ * RD * C_];      // [h][r*D+d][i]
__device__ float  g_Sp [(size_t)H_ * KSPLIT * C_ * C_];
__device__ __half g_P  [(size_t)H_ * C_ * C_];
__device__ __half g_ctx[(size_t)M_TOK * E_];

// ---------------------------------------------------------------------------
// Helpers
// ---------------------------------------------------------------------------
__device__ __forceinline__ uint32_t smem_u32(const void* p) {
    uint32_t a;
    asm("{ .reg .u64 t; cvta.to.shared.u64 t, %1; cvt.u32.u64 %0, t; }"
        : "=r"(a) : "l"(p));
    return a;
}
__device__ __forceinline__ void cpa16(uint32_t dst, const void* src) {
    asm volatile("cp.async.cg.shared.global [%0], [%1], 16;"
                 :: "r"(dst), "l"(src) : "memory");
}
__device__ __forceinline__ void ldsm4(uint32_t& r0, uint32_t& r1,
                                      uint32_t& r2, uint32_t& r3, uint32_t addr) {
    asm volatile("ldmatrix.sync.aligned.m8n8.x4.shared.b16 {%0,%1,%2,%3}, [%4];"
                 : "=r"(r0), "=r"(r1), "=r"(r2), "=r"(r3) : "r"(addr));
}

__global__ void __launch_bounds__(256)
f2h_kernel(const float* __restrict__ in, __half* __restrict__ out, int n4) {
    int i = blockIdx.x * blockDim.x + threadIdx.x;
    if (i < n4) {
        float4 v = ((const float4*)in)[i];
        __half2* o = (__half2*)(out + (size_t)i * 4);
        o[0] = __floats2half2_rn(v.x, v.y);
        o[1] = __floats2half2_rn(v.z, v.w);
    }
}

__global__ void __launch_bounds__(256)
f2h_w_kernel(const float* __restrict__ w0, const float* __restrict__ w1,
             const float* __restrict__ w2, const float* __restrict__ w3,
             __half* __restrict__ out, int n4) {
    int i = blockIdx.x * blockDim.x + threadIdx.x;
    if (i >= n4) return;
    const float* src = (blockIdx.y == 0) ? w0 : (blockIdx.y == 1) ? w1
                      : (blockIdx.y == 2) ? w2 : w3;
    float4 v = ((const float4*)src)[i];
    __half2* o = (__half2*)(out + (size_t)blockIdx.y * E_ * E_ + (size_t)i * 4);
    o[0] = __floats2half2_rn(v.x, v.y);
    o[1] = __floats2half2_rn(v.z, v.w);
}

// ---------------------------------------------------------------------------
// fp16 mma.sync GEMM, fp32 accumulate. Block 128x128x64, 8 warps (4m x 2n),
// warp tile 32x64. 3-stage cp.async pipeline, BK=64, register-level
// fragment double-buffering. 2 CTAs/SM.
// ---------------------------------------------------------------------------
constexpr int BM = 128, BN = 128, BK = 64;
constexpr int STAGES = 3;
constexpr int AS_STRIDE = 72;                     // halves per row (144 B)
constexpr int BS_STRIDE = 72;
constexpr int AS_HALVES = BM * AS_STRIDE;         // 9216
constexpr int BS_HALVES = BN * BS_STRIDE;         // 9216
constexpr int STAGE_HALVES = AS_HALVES + BS_HALVES;   // 18432 (36864 B)
constexpr int SMEM_BYTES = STAGES * STAGE_HALVES * 2; // 110592

enum { EPI_PROJ = 0, EPI_LOGITS = 2, EPI_CTX = 3, EPI_OPROJ = 4 };

template <int EPI>
__global__ void __launch_bounds__(256, 2)
mm_kernel(const __half* __restrict__ A, const __half* __restrict__ Bw,
          const float* __restrict__ biasQ, const float* __restrict__ biasK,
          const float* __restrict__ biasV,
          __half* __restrict__ dQ, __half* __restrict__ dK, __half* __restrict__ dVt,
          float* __restrict__ CoutF, __half* __restrict__ CoutH,
          int lda, int ldb, int K)
{
    extern __shared__ __half sm[];
    const int tid = threadIdx.x;
    const int wid = tid >> 5, lane = tid & 31;
    const int m0 = blockIdx.y * BM;
    const int n0 = blockIdx.x * BN;
    const int z  = blockIdx.z;

    const __half* B = Bw;
    if (EPI == EPI_PROJ)   { B  = Bw + (size_t)z * E_ * E_; }
    if (EPI == EPI_LOGITS) {
        const int head = z >> 2, kh = z & 3;
        A += (size_t)head * RD + (size_t)kh * KPART;
        B  = Bw + (size_t)head * RD + (size_t)kh * KPART;
    }
    if (EPI == EPI_CTX)    { A += (size_t)z * C_ * C_; B = Bw + (size_t)z * RD * C_; }

    const uint32_t smb = smem_u32(sm);

    const int warp_m = wid >> 1;          // 0..3 -> 32-row slices
    const int warp_n = wid & 1;           // 0..1 -> 64-col slices
    const int mb_base = warp_m * 32;
    const int nb_base = warp_n * 64;
    const int r4 = lane >> 2, c4 = lane & 3;

    const uint32_t a_off =
        (uint32_t)(((mb_base + (lane & 15)) * AS_STRIDE + ((lane >> 4) * 8)) * 2);
    const uint32_t b_off =
        (uint32_t)(((nb_base + (lane & 7) + ((lane & 16) >> 1)) * BS_STRIDE +
                    (((lane >> 3) & 1) * 8)) * 2);

    float acc[2][8][4];
#pragma unroll
    for (int a = 0; a < 2; a++)
#pragma unroll
        for (int b = 0; b < 8; b++)
#pragma unroll
            for (int c = 0; c < 4; c++) acc[a][b][c] = 0.f;

    const int NC = K / BK;

    auto load_stage = [&](int c, int s) {
        const __half* Ab = A + (size_t)m0 * lda + c * BK;
        const __half* Bb = B + (size_t)n0 * ldb + c * BK;
        const uint32_t asb = smb + (uint32_t)(s * STAGE_HALVES) * 2u;
        const uint32_t bsb = asb + AS_HALVES * 2u;
#pragma unroll
        for (int i = 0; i < 4; i++) {          // A: 128 rows x 8 f8 = 1024 cp
            int q = i * 256 + tid;
            int row = q >> 3, kq = q & 7;
            cpa16(asb + (uint32_t)(row * AS_STRIDE + kq * 8) * 2u,
                  Ab + (size_t)row * lda + kq * 8);
        }
#pragma unroll
        for (int i = 0; i < 4; i++) {          // B: 128 rows x 8 f8 = 1024 cp
            int q = i * 256 + tid;
            int row = q >> 3, kq = q & 7;
            cpa16(bsb + (uint32_t)(row * BS_STRIDE + kq * 8) * 2u,
                  Bb + (size_t)row * ldb + kq * 8);
        }
        asm volatile("cp.async.commit_group;" ::: "memory");
    };

#pragma unroll
    for (int s = 0; s < STAGES - 1; s++)
        if (s < NC) load_stage(s, s);

    uint32_t afr[2][2][4], bfr[2][8][2];   // double-buffered fragments

    int sidx = 0;
    for (int c = 0; c < NC; c++) {
        asm volatile("cp.async.wait_group %0;" :: "n"(STAGES - 2) : "memory");
        __syncthreads();

        const int cn = c + STAGES - 1;
        if (cn < NC) {
            int sn = sidx + STAGES - 1; if (sn >= STAGES) sn -= STAGES;
            load_stage(cn, sn);
        }

        const uint32_t abase = smb + (uint32_t)(sidx * STAGE_HALVES) * 2u + a_off;
        const uint32_t bbase = smb + (uint32_t)(sidx * STAGE_HALVES + AS_HALVES) * 2u + b_off;

        // prime substep 0 fragments
#pragma unroll
        for (int mb = 0; mb < 2; mb++)
            ldsm4(afr[0][mb][0], afr[0][mb][1], afr[0][mb][2], afr[0][mb][3],
                  abase + (uint32_t)((mb * 16 * AS_STRIDE) * 2));
#pragma unroll
        for (int p = 0; p < 4; p++)
            ldsm4(bfr[0][2*p][0], bfr[0][2*p][1], bfr[0][2*p+1][0], bfr[0][2*p+1][1],
                  bbase + (uint32_t)((p * 16 * BS_STRIDE) * 2));

#pragma unroll
        for (int s = 0; s < 4; s++) {          // 4 substeps of k16
            const int cur = s & 1, nxt = cur ^ 1;
            if (s < 3) {
                const int ks = (s + 1) * 16;
#pragma unroll
                for (int mb = 0; mb < 2; mb++)
                    ldsm4(afr[nxt][mb][0], afr[nxt][mb][1],
                          afr[nxt][mb][2], afr[nxt][mb][3],
                          abase + (uint32_t)((mb * 16 * AS_STRIDE + ks) * 2));
#pragma unroll
                for (int p = 0; p < 4; p++)
                    ldsm4(bfr[nxt][2*p][0], bfr[nxt][2*p][1],
                          bfr[nxt][2*p+1][0], bfr[nxt][2*p+1][1],
                          bbase + (uint32_t)((p * 16 * BS_STRIDE + ks) * 2));
            }
#pragma unroll
            for (int mb = 0; mb < 2; mb++)
#pragma unroll
                for (int nb = 0; nb < 8; nb++) {
                    asm volatile(
                        "mma.sync.aligned.m16n8k16.row.col.f32.f16.f16.f32 "
                        "{%0,%1,%2,%3}, {%4,%5,%6,%7}, {%8,%9}, {%0,%1,%2,%3};"
                        : "+f"(acc[mb][nb][0]), "+f"(acc[mb][nb][1]),
                          "+f"(acc[mb][nb][2]), "+f"(acc[mb][nb][3])
                        : "r"(afr[cur][mb][0]), "r"(afr[cur][mb][1]),
                          "r"(afr[cur][mb][2]), "r"(afr[cur][mb][3]),
                          "r"(bfr[cur][nb][0]), "r"(bfr[cur][nb][1]));
                }
        }
        if (++sidx == STAGES) sidx = 0;
    }

    // ---- epilogue
#pragma unroll
    for (int mb = 0; mb < 2; mb++) {
#pragma unroll
        for (int half_ = 0; half_ < 2; half_++) {
            const int m = m0 + mb_base + mb * 16 + r4 + half_ * 8;
#pragma unroll
            for (int nb = 0; nb < 8; nb++) {
                const int n = n0 + nb_base + nb * 8 + c4 * 2;
                float v0 = acc[mb][nb][half_ * 2 + 0];
                float v1 = acc[mb][nb][half_ * 2 + 1];

                if (EPI == EPI_PROJ) {
                    const int r = m >> 9, ic = m & 511;
                    const int h = n >> 6, d = n & 63;
                    if (z == 0) {
                        v0 = (v0 + biasQ[n])     * SCALING;
                        v1 = (v1 + biasQ[n + 1]) * SCALING;
                        *(__half2*)(dQ + (((size_t)ic * H_ + h) * R_ + r) * D_ + d) =
                            __floats2half2_rn(v0, v1);
                    } else if (z == 1) {
                        v0 += biasK[n]; v1 += biasK[n + 1];
                        *(__half2*)(dK + (((size_t)ic * H_ + h) * R_ + r) * D_ + d) =
                            __floats2half2_rn(v0, v1);
                    } else {
                        v0 += biasV[n]; v1 += biasV[n + 1];
                        __half* dst = dVt + ((size_t)h * RD + r * D_ + d) * C_ + ic;
                        dst[0]  = __float2half_rn(v0);
                        dst[C_] = __float2half_rn(v1);
                    }
                } else if (EPI == EPI_LOGITS) {
                    float2* dst = (float2*)(CoutF + ((size_t)z * C_ + m) * C_ + n);
                    *dst = make_float2(v0, v1);
                } else if (EPI == EPI_CTX) {
                    const int r = n >> 6, d = n & 63;
                    *(__half2*)(CoutH + ((size_t)(r * C_) + m) * E_ + z * D_ + d) =
                        __floats2half2_rn(v0, v1);
                } else { // EPI_OPROJ
                    float2* dst = (float2*)(CoutF + (size_t)m * E_ + n);
                    *dst = make_float2(v0 + biasQ[n], v1 + biasQ[n + 1]);
                }
            }
        }
    }
}

// ---------------------------------------------------------------------------
// Masked softmax; sums KSPLIT partials. fp32 to d_out, fp16 to P.
// ---------------------------------------------------------------------------
__global__ void __launch_bounds__(512)
softmax_kernel(const float* __restrict__ Sp, __half* __restrict__ P,
               float* __restrict__ Pout)
{
    const int row = blockIdx.x;
    const int h   = row >> 9;
    const int i   = row & (C_ - 1);
    const int j   = threadIdx.x;
    const int lane = j & 31, warp = j >> 5;
    __shared__ float red[16];

    const float* base = Sp + (((size_t)h * KSPLIT) * C_ + i) * C_ + j;
    float x = base[0];
#pragma unroll
    for (int kh = 1; kh < KSPLIT; kh++)
        x += base[(size_t)kh * C_ * C_];
    if (j == i) x = -1e9f;

    float m = x;
#pragma unroll
    for (int o = 16; o > 0; o >>= 1) m = fmaxf(m, __shfl_xor_sync(~0u, m, o));
    if (lane == 0) red[warp] = m;
    __syncthreads();
    if (j < 16) {
        float t = red[j];
#pragma unroll
        for (int o = 8; o > 0; o >>= 1) t = fmaxf(t, __shfl_xor_sync(0xffffu, t, o));
        if (j == 0) red[0] = t;
    }
    __syncthreads();
    const float mx = red[0];
    __syncthreads();

    float e = __expf(x - mx);
    float sacc = e;
#pragma unroll
    for (int o = 16; o > 0; o >>= 1) sacc += __shfl_xor_sync(~0u, sacc, o);
    if (lane == 0) red[warp] = sacc;
    __syncthreads();
    if (j < 16) {
        float t = red[j];
#pragma unroll
        for (int o = 8; o > 0; o >>= 1) t += __shfl_xor_sync(0xffffu, t, o);
        if (j == 0) red[0] = t;
    }
    __syncthreads();
    const float inv = 1.0f / red[0];

    const float p = e * inv;
    const size_t idx = (size_t)row * C_ + j;
    P[idx]    = __float2half_rn(p);
    Pout[idx] = p;
}

__global__ void copy_l_kernel(const float* __restrict__ l, float* __restrict__ out)
{
    if (threadIdx.x < H_) out[threadIdx.x] = l[threadIdx.x];
}

// ---------------------------------------------------------------------------
// Launch
// ---------------------------------------------------------------------------
extern "C" void kernel_launch(void* const* d_in, const int* in_sizes, int n_in,
                              void* d_out, int out_size)
{
    const float* x  = (const float*)d_in[0];
    const float* Wq = (const float*)d_in[2];
    const float* bq = (const float*)d_in[3];
    const float* Wk = (const float*)d_in[4];
    const float* bk = (const float*)d_in[5];
    const float* Wv = (const float*)d_in[6];
    const float* bv = (const float*)d_in[7];
    const float* Wo = (const float*)d_in[8];
    const float* bo = (const float*)d_in[9];
    const float* l  = (const float*)d_in[10];
    float* out = (float*)d_out;

    __half *pXh, *pWh, *pQ, *pK, *pVt, *pP, *pCtx;
    float *pSp;
    cudaGetSymbolAddress((void**)&pXh,  g_xh);
    cudaGetSymbolAddress((void**)&pWh,  g_Wh);
    cudaGetSymbolAddress((void**)&pQ,   g_Q);
    cudaGetSymbolAddress((void**)&pK,   g_K);
    cudaGetSymbolAddress((void**)&pVt,  g_Vt);
    cudaGetSymbolAddress((void**)&pSp,  g_Sp);
    cudaGetSymbolAddress((void**)&pP,   g_P);
    cudaGetSymbolAddress((void**)&pCtx, g_ctx);

    cudaFuncSetAttribute(mm_kernel<EPI_PROJ>,   cudaFuncAttributeMaxDynamicSharedMemorySize, SMEM_BYTES);
    cudaFuncSetAttribute(mm_kernel<EPI_LOGITS>, cudaFuncAttributeMaxDynamicSharedMemorySize, SMEM_BYTES);
    cudaFuncSetAttribute(mm_kernel<EPI_CTX>,    cudaFuncAttributeMaxDynamicSharedMemorySize, SMEM_BYTES);
    cudaFuncSetAttribute(mm_kernel<EPI_OPROJ>,  cudaFuncAttributeMaxDynamicSharedMemorySize, SMEM_BYTES);

    const size_t WSZ = (size_t)E_ * E_;

    // 0) fp16 conversion
    {
        int n4x = (int)((size_t)M_TOK * E_ / 4);
        f2h_kernel<<<(n4x + 255) / 256, 256>>>(x, pXh, n4x);
        int n4w = (int)(WSZ / 4);
        dim3 gW((n4w + 255) / 256, 4);
        f2h_w_kernel<<<gW, 256>>>(Wq, Wk, Wv, Wo, pWh, n4w);
    }

    const dim3 gProj (E_ / BN, M_TOK / BM, 3);          // 6 x 256 x 3
    const dim3 gLog  (C_ / BN, C_ / BM, H_ * KSPLIT);   // 4 x 4 x 48
    const dim3 gCtx  (RD / BN, C_ / BM, H_);            // 32 x 4 x 12
    const dim3 gOut  (E_ / BN, M_TOK / BM, 1);          // 6 x 256

    // 1) fused Q/K/V projections
    mm_kernel<EPI_PROJ><<<gProj, 256, SMEM_BYTES>>>(
        pXh, pWh, bq, bk, bv, pQ, pK, pVt, nullptr, nullptr, E_, E_, E_);

    // 2) tied-row logits, split-K x4
    mm_kernel<EPI_LOGITS><<<gLog, 256, SMEM_BYTES>>>(
        pQ, pK, nullptr, nullptr, nullptr, nullptr, nullptr, nullptr,
        pSp, nullptr, HRD, HRD, KPART);

    // 3) masked softmax
    softmax_kernel<<<H_ * C_, 512>>>(pSp, pP, out + OUT_OFF_P);

    // 4) context
    mm_kernel<EPI_CTX><<<gCtx, 256, SMEM_BYTES>>>(
        pP, pVt, nullptr, nullptr, nullptr, nullptr, nullptr, nullptr,
        nullptr, pCtx, C_, C_, C_);

    // 5) output projection
    mm_kernel<EPI_OPROJ><<<gOut, 256, SMEM_BYTES>>>(
        pCtx, pWh + 3 * WSZ, bo, nullptr, nullptr, nullptr, nullptr, nullptr,
        out, nullptr, E_, E_, E_);

    // 6) l passthrough
    copy_l_kernel<<<1, 32>>>(l, out + OUT_OFF_L);
}

// round 9
// speedup vs baseline: 7.5352x; 1.0008x over previous
#include <cuda_runtime.h>
#include <cuda_fp16.h>
#include <cstdint>

// ---------------------------------------------------------------------------
// Problem constants
// ---------------------------------------------------------------------------
constexpr int R_ = 64, C_ = 512, H_ = 12, D_ = 64, E_ = 768;
constexpr int M_TOK = R_ * C_;   // 32768
constexpr int RD    = R_ * D_;   // 4096
constexpr int HRD   = H_ * RD;   // 49152
constexpr long OUT_OFF_P = (long)M_TOK * E_;
constexpr long OUT_OFF_L = OUT_OFF_P + (long)H_ * C_ * C_;
constexpr float SCALING = 0.015625f;  // D^-0.5 / sqrt(R)
constexpr int KSPLIT = 4;
constexpr int KPART  = RD / KSPLIT;   // 1024

// ---------------------------------------------------------------------------
// Scratch
// ---------------------------------------------------------------------------
__device__ __half g_xh [(size_t)M_TOK * E_];
__device__ __half g_Wh [4 * (size_t)E_ * E_];
__device__ __half g_Q  [(size_t)C_ * HRD];          // [i][h][r][d]
__device__ __half g_K  [(size_t)C_ * HRD];          // [i][h][r][d]
__device__ __half g_Vt [(size_t)H_ * RD * C_];      // [h][r*D+d][i]
__device__ float  g_Sp [(size_t)H_ * KSPLIT * C_ * C_];
__device__ __half g_P  [(size_t)H_ * C_ * C_];
__device__ __half g_ctx[(size_t)M_TOK * E_];

// ---------------------------------------------------------------------------
// Helpers
// ---------------------------------------------------------------------------
__device__ __forceinline__ uint32_t smem_u32(const void* p) {
    uint32_t a;
    asm("{ .reg .u64 t; cvta.to.shared.u64 t, %1; cvt.u32.u64 %0, t; }"
        : "=r"(a) : "l"(p));
    return a;
}
__device__ __forceinline__ void cpa16(uint32_t dst, const void* src) {
    asm volatile("cp.async.cg.shared.global [%0], [%1], 16;"
                 :: "r"(dst), "l"(src) : "memory");
}
__device__ __forceinline__ void ldsm4(uint32_t& r0, uint32_t& r1,
                                      uint32_t& r2, uint32_t& r3, uint32_t addr) {
    asm volatile("ldmatrix.sync.aligned.m8n8.x4.shared.b16 {%0,%1,%2,%3}, [%4];"
                 : "=r"(r0), "=r"(r1), "=r"(r2), "=r"(r3) : "r"(addr));
}

__global__ void __launch_bounds__(256)
f2h_kernel(const float* __restrict__ in, __half* __restrict__ out, int n4) {
    int i = blockIdx.x * blockDim.x + threadIdx.x;
    if (i < n4) {
        float4 v = ((const float4*)in)[i];
        __half2* o = (__half2*)(out + (size_t)i * 4);
        o[0] = __floats2half2_rn(v.x, v.y);
        o[1] = __floats2half2_rn(v.z, v.w);
    }
}

__global__ void __launch_bounds__(256)
f2h_w_kernel(const float* __restrict__ w0, const float* __restrict__ w1,
             const float* __restrict__ w2, const float* __restrict__ w3,
             __half* __restrict__ out, int n4) {
    int i = blockIdx.x * blockDim.x + threadIdx.x;
    if (i >= n4) return;
    const float* src = (blockIdx.y == 0) ? w0 : (blockIdx.y == 1) ? w1
                      : (blockIdx.y == 2) ? w2 : w3;
    float4 v = ((const float4*)src)[i];
    __half2* o = (__half2*)(out + (size_t)blockIdx.y * E_ * E_ + (size_t)i * 4);
    o[0] = __floats2half2_rn(v.x, v.y);
    o[1] = __floats2half2_rn(v.z, v.w);
}

// ---------------------------------------------------------------------------
// fp16 mma.sync GEMM, fp32 accumulate. Block 128x128x64, 8 warps (4m x 2n),
// warp tile 32x64. 3-stage cp.async pipeline, BK=64, register-level
// fragment double-buffering. 2 CTAs/SM.
// ---------------------------------------------------------------------------
constexpr int BM = 128, BN = 128, BK = 64;
constexpr int STAGES = 3;
constexpr int AS_STRIDE = 72;                     // halves per row (144 B)
constexpr int BS_STRIDE = 72;
constexpr int AS_HALVES = BM * AS_STRIDE;         // 9216
constexpr int BS_HALVES = BN * BS_STRIDE;         // 9216
constexpr int STAGE_HALVES = AS_HALVES + BS_HALVES;   // 18432 (36864 B)
constexpr int SMEM_BYTES = STAGES * STAGE_HALVES * 2; // 110592

enum { EPI_PROJ = 0, EPI_LOGITS = 2, EPI_CTX = 3, EPI_OPROJ = 4 };

template <int EPI>
__global__ void __launch_bounds__(256, 2)
mm_kernel(const __half* __restrict__ A, const __half* __restrict__ Bw,
          const float* __restrict__ biasQ, const float* __restrict__ biasK,
          const float* __restrict__ biasV,
          __half* __restrict__ dQ, __half* __restrict__ dK, __half* __restrict__ dVt,
          float* __restrict__ CoutF, __half* __restrict__ CoutH,
          int lda, int ldb, int K)
{
    extern __shared__ __half sm[];
    const int tid = threadIdx.x;
    const int wid = tid >> 5, lane = tid & 31;
    const int m0 = blockIdx.y * BM;
    const int n0 = blockIdx.x * BN;
    const int z  = blockIdx.z;

    const __half* B = Bw;
    if (EPI == EPI_PROJ)   { B  = Bw + (size_t)z * E_ * E_; }
    if (EPI == EPI_LOGITS) {
        const int head = z >> 2, kh = z & 3;
        A += (size_t)head * RD + (size_t)kh * KPART;
        B  = Bw + (size_t)head * RD + (size_t)kh * KPART;
    }
    if (EPI == EPI_CTX)    { A += (size_t)z * C_ * C_; B = Bw + (size_t)z * RD * C_; }

    const uint32_t smb = smem_u32(sm);

    const int warp_m = wid >> 1;          // 0..3 -> 32-row slices
    const int warp_n = wid & 1;           // 0..1 -> 64-col slices
    const int mb_base = warp_m * 32;
    const int nb_base = warp_n * 64;
    const int r4 = lane >> 2, c4 = lane & 3;

    const uint32_t a_off =
        (uint32_t)(((mb_base + (lane & 15)) * AS_STRIDE + ((lane >> 4) * 8)) * 2);
    const uint32_t b_off =
        (uint32_t)(((nb_base + (lane & 7) + ((lane & 16) >> 1)) * BS_STRIDE +
                    (((lane >> 3) & 1) * 8)) * 2);

    float acc[2][8][4];
#pragma unroll
    for (int a = 0; a < 2; a++)
#pragma unroll
        for (int b = 0; b < 8; b++)
#pragma unroll
            for (int c = 0; c < 4; c++) acc[a][b][c] = 0.f;

    const int NC = K / BK;

    auto load_stage = [&](int c, int s) {
        const __half* Ab = A + (size_t)m0 * lda + c * BK;
        const __half* Bb = B + (size_t)n0 * ldb + c * BK;
        const uint32_t asb = smb + (uint32_t)(s * STAGE_HALVES) * 2u;
        const uint32_t bsb = asb + AS_HALVES * 2u;
#pragma unroll
        for (int i = 0; i < 4; i++) {          // A: 128 rows x 8 f8 = 1024 cp
            int q = i * 256 + tid;
            int row = q >> 3, kq = q & 7;
            cpa16(asb + (uint32_t)(row * AS_STRIDE + kq * 8) * 2u,
                  Ab + (size_t)row * lda + kq * 8);
        }
#pragma unroll
        for (int i = 0; i < 4; i++) {          // B: 128 rows x 8 f8 = 1024 cp
            int q = i * 256 + tid;
            int row = q >> 3, kq = q & 7;
            cpa16(bsb + (uint32_t)(row * BS_STRIDE + kq * 8) * 2u,
                  Bb + (size_t)row * ldb + kq * 8);
        }
        asm volatile("cp.async.commit_group;" ::: "memory");
    };

#pragma unroll
    for (int s = 0; s < STAGES - 1; s++)
        if (s < NC) load_stage(s, s);

    uint32_t afr[2][2][4], bfr[2][8][2];   // double-buffered fragments

    int sidx = 0;
    for (int c = 0; c < NC; c++) {
        asm volatile("cp.async.wait_group %0;" :: "n"(STAGES - 2) : "memory");
        __syncthreads();

        const int cn = c + STAGES - 1;
        if (cn < NC) {
            int sn = sidx + STAGES - 1; if (sn >= STAGES) sn -= STAGES;
            load_stage(cn, sn);
        }

        const uint32_t abase = smb + (uint32_t)(sidx * STAGE_HALVES) * 2u + a_off;
        const uint32_t bbase = smb + (uint32_t)(sidx * STAGE_HALVES + AS_HALVES) * 2u + b_off;

        // prime substep 0 fragments
#pragma unroll
        for (int mb = 0; mb < 2; mb++)
            ldsm4(afr[0][mb][0], afr[0][mb][1], afr[0][mb][2], afr[0][mb][3],
                  abase + (uint32_t)((mb * 16 * AS_STRIDE) * 2));
#pragma unroll
        for (int p = 0; p < 4; p++)
            ldsm4(bfr[0][2*p][0], bfr[0][2*p][1], bfr[0][2*p+1][0], bfr[0][2*p+1][1],
                  bbase + (uint32_t)((p * 16 * BS_STRIDE) * 2));

#pragma unroll
        for (int s = 0; s < 4; s++) {          // 4 substeps of k16
            const int cur = s & 1, nxt = cur ^ 1;
            if (s < 3) {
                const int ks = (s + 1) * 16;
#pragma unroll
                for (int mb = 0; mb < 2; mb++)
                    ldsm4(afr[nxt][mb][0], afr[nxt][mb][1],
                          afr[nxt][mb][2], afr[nxt][mb][3],
                          abase + (uint32_t)((mb * 16 * AS_STRIDE + ks) * 2));
#pragma unroll
                for (int p = 0; p < 4; p++)
                    ldsm4(bfr[nxt][2*p][0], bfr[nxt][2*p][1],
                          bfr[nxt][2*p+1][0], bfr[nxt][2*p+1][1],
                          bbase + (uint32_t)((p * 16 * BS_STRIDE + ks) * 2));
            }
#pragma unroll
            for (int mb = 0; mb < 2; mb++)
#pragma unroll
                for (int nb = 0; nb < 8; nb++) {
                    asm volatile(
                        "mma.sync.aligned.m16n8k16.row.col.f32.f16.f16.f32 "
                        "{%0,%1,%2,%3}, {%4,%5,%6,%7}, {%8,%9}, {%0,%1,%2,%3};"
                        : "+f"(acc[mb][nb][0]), "+f"(acc[mb][nb][1]),
                          "+f"(acc[mb][nb][2]), "+f"(acc[mb][nb][3])
                        : "r"(afr[cur][mb][0]), "r"(afr[cur][mb][1]),
                          "r"(afr[cur][mb][2]), "r"(afr[cur][mb][3]),
                          "r"(bfr[cur][nb][0]), "r"(bfr[cur][nb][1]));
                }
        }
        if (++sidx == STAGES) sidx = 0;
    }

    // ---- epilogue
#pragma unroll
    for (int mb = 0; mb < 2; mb++) {
#pragma unroll
        for (int half_ = 0; half_ < 2; half_++) {
            const int m = m0 + mb_base + mb * 16 + r4 + half_ * 8;
#pragma unroll
            for (int nb = 0; nb < 8; nb++) {
                const int n = n0 + nb_base + nb * 8 + c4 * 2;
                float v0 = acc[mb][nb][half_ * 2 + 0];
                float v1 = acc[mb][nb][half_ * 2 + 1];

                if (EPI == EPI_PROJ) {
                    const int r = m >> 9, ic = m & 511;
                    const int h = n >> 6, d = n & 63;
                    if (z == 0) {
                        v0 = (v0 + biasQ[n])     * SCALING;
                        v1 = (v1 + biasQ[n + 1]) * SCALING;
                        *(__half2*)(dQ + (((size_t)ic * H_ + h) * R_ + r) * D_ + d) =
                            __floats2half2_rn(v0, v1);
                    } else if (z == 1) {
                        v0 += biasK[n]; v1 += biasK[n + 1];
                        *(__half2*)(dK + (((size_t)ic * H_ + h) * R_ + r) * D_ + d) =
                            __floats2half2_rn(v0, v1);
                    } else {
                        v0 += biasV[n]; v1 += biasV[n + 1];
                        __half* dst = dVt + ((size_t)h * RD + r * D_ + d) * C_ + ic;
                        dst[0]  = __float2half_rn(v0);
                        dst[C_] = __float2half_rn(v1);
                    }
                } else if (EPI == EPI_LOGITS) {
                    float2* dst = (float2*)(CoutF + ((size_t)z * C_ + m) * C_ + n);
                    *dst = make_float2(v0, v1);
                } else if (EPI == EPI_CTX) {
                    const int r = n >> 6, d = n & 63;
                    *(__half2*)(CoutH + ((size_t)(r * C_) + m) * E_ + z * D_ + d) =
                        __floats2half2_rn(v0, v1);
                } else { // EPI_OPROJ
                    float2* dst = (float2*)(CoutF + (size_t)m * E_ + n);
                    *dst = make_float2(v0 + biasQ[n], v1 + biasQ[n + 1]);
                }
            }
        }
    }
}

// ---------------------------------------------------------------------------
// Masked softmax; sums KSPLIT partials. fp32 to d_out, fp16 to P.
// ---------------------------------------------------------------------------
__global__ void __launch_bounds__(512)
softmax_kernel(const float* __restrict__ Sp, __half* __restrict__ P,
               float* __restrict__ Pout)
{
    const int row = blockIdx.x;
    const int h   = row >> 9;
    const int i   = row & (C_ - 1);
    const int j   = threadIdx.x;
    const int lane = j & 31, warp = j >> 5;
    __shared__ float red[16];

    const float* base = Sp + (((size_t)h * KSPLIT) * C_ + i) * C_ + j;
    float x = base[0];
#pragma unroll
    for (int kh = 1; kh < KSPLIT; kh++)
        x += base[(size_t)kh * C_ * C_];
    if (j == i) x = -1e9f;

    float m = x;
#pragma unroll
    for (int o = 16; o > 0; o >>= 1) m = fmaxf(m, __shfl_xor_sync(~0u, m, o));
    if (lane == 0) red[warp] = m;
    __syncthreads();
    if (j < 16) {
        float t = red[j];
#pragma unroll
        for (int o = 8; o > 0; o >>= 1) t = fmaxf(t, __shfl_xor_sync(0xffffu, t, o));
        if (j == 0) red[0] = t;
    }
    __syncthreads();
    const float mx = red[0];
    __syncthreads();

    float e = __expf(x - mx);
    float sacc = e;
#pragma unroll
    for (int o = 16; o > 0; o >>= 1) sacc += __shfl_xor_sync(~0u, sacc, o);
    if (lane == 0) red[warp] = sacc;
    __syncthreads();
    if (j < 16) {
        float t = red[j];
#pragma unroll
        for (int o = 8; o > 0; o >>= 1) t += __shfl_xor_sync(0xffffu, t, o);
        if (j == 0) red[0] = t;
    }
    __syncthreads();
    const float inv = 1.0f / red[0];

    const float p = e * inv;
    const size_t idx = (size_t)row * C_ + j;
    P[idx]    = __float2half_rn(p);
    Pout[idx] = p;
}

__global__ void copy_l_kernel(const float* __restrict__ l, float* __restrict__ out)
{
    if (threadIdx.x < H_) out[threadIdx.x] = l[threadIdx.x];
}

// ---------------------------------------------------------------------------
// Launch
// ---------------------------------------------------------------------------
extern "C" void kernel_launch(void* const* d_in, const int* in_sizes, int n_in,
                              void* d_out, int out_size)
{
    const float* x  = (const float*)d_in[0];
    const float* Wq = (const float*)d_in[2];
    const float* bq = (const float*)d_in[3];
    const float* Wk = (const float*)d_in[4];
    const float* bk = (const float*)d_in[5];
    const float* Wv = (const float*)d_in[6];
    const float* bv = (const float*)d_in[7];
    const float* Wo = (const float*)d_in[8];
    const float* bo = (const float*)d_in[9];
    const float* l  = (const float*)d_in[10];
    float* out = (float*)d_out;

    __half *pXh, *pWh, *pQ, *pK, *pVt, *pP, *pCtx;
    float *pSp;
    cudaGetSymbolAddress((void**)&pXh,  g_xh);
    cudaGetSymbolAddress((void**)&pWh,  g_Wh);
    cudaGetSymbolAddress((void**)&pQ,   g_Q);
    cudaGetSymbolAddress((void**)&pK,   g_K);
    cudaGetSymbolAddress((void**)&pVt,  g_Vt);
    cudaGetSymbolAddress((void**)&pSp,  g_Sp);
    cudaGetSymbolAddress((void**)&pP,   g_P);
    cudaGetSymbolAddress((void**)&pCtx, g_ctx);

    cudaFuncSetAttribute(mm_kernel<EPI_PROJ>,   cudaFuncAttributeMaxDynamicSharedMemorySize, SMEM_BYTES);
    cudaFuncSetAttribute(mm_kernel<EPI_LOGITS>, cudaFuncAttributeMaxDynamicSharedMemorySize, SMEM_BYTES);
    cudaFuncSetAttribute(mm_kernel<EPI_CTX>,    cudaFuncAttributeMaxDynamicSharedMemorySize, SMEM_BYTES);
    cudaFuncSetAttribute(mm_kernel<EPI_OPROJ>,  cudaFuncAttributeMaxDynamicSharedMemorySize, SMEM_BYTES);

    const size_t WSZ = (size_t)E_ * E_;

    // 0) fp16 conversion
    {
        int n4x = (int)((size_t)M_TOK * E_ / 4);
        f2h_kernel<<<(n4x + 255) / 256, 256>>>(x, pXh, n4x);
        int n4w = (int)(WSZ / 4);
        dim3 gW((n4w + 255) / 256, 4);
        f2h_w_kernel<<<gW, 256>>>(Wq, Wk, Wv, Wo, pWh, n4w);
    }

    const dim3 gProj (E_ / BN, M_TOK / BM, 3);          // 6 x 256 x 3
    const dim3 gLog  (C_ / BN, C_ / BM, H_ * KSPLIT);   // 4 x 4 x 48
    const dim3 gCtx  (RD / BN, C_ / BM, H_);            // 32 x 4 x 12
    const dim3 gOut  (E_ / BN, M_TOK / BM, 1);          // 6 x 256

    // 1) fused Q/K/V projections
    mm_kernel<EPI_PROJ><<<gProj, 256, SMEM_BYTES>>>(
        pXh, pWh, bq, bk, bv, pQ, pK, pVt, nullptr, nullptr, E_, E_, E_);

    // 2) tied-row logits, split-K x4
    mm_kernel<EPI_LOGITS><<<gLog, 256, SMEM_BYTES>>>(
        pQ, pK, nullptr, nullptr, nullptr, nullptr, nullptr, nullptr,
        pSp, nullptr, HRD, HRD, KPART);

    // 3) masked softmax
    softmax_kernel<<<H_ * C_, 512>>>(pSp, pP, out + OUT_OFF_P);

    // 4) context
    mm_kernel<EPI_CTX><<<gCtx, 256, SMEM_BYTES>>>(
        pP, pVt, nullptr, nullptr, nullptr, nullptr, nullptr, nullptr,
        nullptr, pCtx, C_, C_, C_);

    // 5) output projection
    mm_kernel<EPI_OPROJ><<<gOut, 256, SMEM_BYTES>>>(
        pCtx, pWh + 3 * WSZ, bo, nullptr, nullptr, nullptr, nullptr, nullptr,
        out, nullptr, E_, E_, E_);

    // 6) l passthrough
    copy_l_kernel<<<1, 32>>>(l, out + OUT_OFF_L);
}